// round 1
// baseline (speedup 1.0000x reference)
#include <cuda_runtime.h>
#include <math.h>

// Problem dims
#define Hd   448
#define Wd   224
#define Dd   12
#define Cd   10
#define HW   100352          // 448*224
#define DHW  1204224         // 12*HW
#define CDHW 12042240        // 10*DHW
#define INV_HW (1.0f/100352.0f)
#define NB_EW 1024           // blocks for elementwise+reduce kernels
#define NB_Q  672            // blocks for K3 (D*H/8)
#define PI_D 3.14159265358979323846

// -------- device scratch (static __device__ arrays: allocation-free) --------
__device__ float2 g_scr[CDHW];     // coil-expanded slices [c][d][h][w]  (96 MB)
__device__ float2 g_p[DHW];
__device__ float2 g_r[DHW];
__device__ float2 g_b[DHW];
__device__ float2 g_q[DHW];
__device__ float2 g_W224[224];
__device__ float2 g_W448[448];
__device__ float  g_rr[8];
__device__ float2 g_alpha[8];
__device__ float  g_beta[8];
__device__ float2 g_qp_part[NB_Q];
__device__ float  g_rr_part[NB_EW];

// -------- complex helpers --------
__device__ __forceinline__ float2 cmulf(float2 a, float2 b) {
    return make_float2(a.x*b.x - a.y*b.y, a.x*b.y + a.y*b.x);
}
__device__ __forceinline__ void cmadd(float2& acc, float2 a, float2 b) {
    acc.x = fmaf(a.x, b.x, fmaf(-a.y, b.y, acc.x));
    acc.y = fmaf(a.x, b.y, fmaf( a.y, b.x, acc.y));
}

// -------- deterministic block reductions --------
__device__ __forceinline__ float blockReduceF(float v) {
    __shared__ float red[8];
    int lane = threadIdx.x & 31, wp = threadIdx.x >> 5;
    #pragma unroll
    for (int o = 16; o > 0; o >>= 1) v += __shfl_down_sync(0xffffffffu, v, o);
    if (lane == 0) red[wp] = v;
    __syncthreads();
    if (wp == 0) {
        v = (lane < 8) ? red[lane] : 0.f;
        #pragma unroll
        for (int o = 4; o > 0; o >>= 1) v += __shfl_down_sync(0xffffffffu, v, o);
    }
    return v;   // valid on thread 0
}
__device__ __forceinline__ float2 blockReduceC(float2 v) {
    __shared__ float2 redc[8];
    int lane = threadIdx.x & 31, wp = threadIdx.x >> 5;
    #pragma unroll
    for (int o = 16; o > 0; o >>= 1) {
        v.x += __shfl_down_sync(0xffffffffu, v.x, o);
        v.y += __shfl_down_sync(0xffffffffu, v.y, o);
    }
    if (lane == 0) redc[wp] = v;
    __syncthreads();
    if (wp == 0) {
        v = (lane < 8) ? redc[lane] : make_float2(0.f, 0.f);
        #pragma unroll
        for (int o = 4; o > 0; o >>= 1) {
            v.x += __shfl_down_sync(0xffffffffu, v.x, o);
            v.y += __shfl_down_sync(0xffffffffu, v.y, o);
        }
    }
    return v;
}

// -------- twiddle init --------
__global__ void k_twiddle() {
    int i = threadIdx.x;
    if (i < 224) {
        double a = -2.0 * PI_D * (double)i / 224.0;
        g_W224[i] = make_float2((float)cos(a), (float)sin(a));
    }
    if (i < 448) {
        double a = -2.0 * PI_D * (double)i / 448.0;
        g_W448[i] = make_float2((float)cos(a), (float)sin(a));
    }
}

// -------- length-224 FFT, one warp per row. n = 32*n1 + n2 (t = n2), k = 7*k2 + k1 (k2 = t).
// Input:  a[n1] = x[32*n1 + t].  Output: out[k1] = X[7*t + k1]. row = 224-slot shared scratch.
template<bool INV>
__device__ __forceinline__ void fft224_warp(float2* row, const float2* Wt, int t,
                                            const float2 a[7], float2 out[7]) {
    float2 y[7];
    #pragma unroll
    for (int k1 = 0; k1 < 7; k1++) {
        float2 acc = make_float2(0.f, 0.f);
        #pragma unroll
        for (int n1 = 0; n1 < 7; n1++) {
            float2 w = Wt[32 * ((n1 * k1) % 7)];
            if (INV) w.y = -w.y;
            cmadd(acc, a[n1], w);
        }
        float2 tw = Wt[t * k1];             // t*k1 <= 186 < 224
        if (INV) tw.y = -tw.y;
        y[k1] = cmulf(acc, tw);
    }
    __syncwarp();
    #pragma unroll
    for (int k1 = 0; k1 < 7; k1++) row[k1 * 32 + t] = y[k1];
    __syncwarp();
    #pragma unroll
    for (int k1 = 0; k1 < 7; k1++) out[k1] = make_float2(0.f, 0.f);
    for (int n2 = 0; n2 < 32; n2++) {
        float2 w = Wt[7 * ((n2 * t) & 31)];
        if (INV) w.y = -w.y;
        #pragma unroll
        for (int k1 = 0; k1 < 7; k1++) cmadd(out[k1], row[k1 * 32 + n2], w);
    }
    __syncwarp();
}

// -------- K0: p = s*(zf + mu*z); r = p; b = 0; partial ||p||^2 --------
__global__ __launch_bounds__(256) void k_init(const float* __restrict__ z,
                                              const float* __restrict__ zf,
                                              const float* __restrict__ miu) {
    float mu = fabsf(miu[0]);
    float rr = 0.f;
    for (int n = blockIdx.x * 256 + threadIdx.x; n < DHW; n += NB_EW * 256) {
        int w = n % Wd;
        int h = (n / Wd) % Hd;
        float s = ((h + w) & 1) ? -1.f : 1.f;
        float pr = s * (zf[n] + mu * z[n]);
        float pi = s * (zf[DHW + n] + mu * z[DHW + n]);
        float2 p = make_float2(pr, pi);
        g_p[n] = p; g_r[n] = p; g_b[n] = make_float2(0.f, 0.f);
        rr = fmaf(pr, pr, fmaf(pi, pi, rr));
    }
    rr = blockReduceF(rr);
    if (threadIdx.x == 0) g_rr_part[blockIdx.x] = rr;
}

__global__ void k_sum_rr0() {
    float v = 0.f;
    for (int i = threadIdx.x; i < NB_EW; i += 256) v += g_rr_part[i];
    v = blockReduceF(v);
    if (threadIdx.x == 0) g_rr[0] = v;
}

// -------- K1: forward row FFTs with coil expand. grid = C*D*H/8 CTAs, 1 warp per row --------
__global__ __launch_bounds__(256) void k_rowfft_fwd(const float* __restrict__ cr,
                                                    const float* __restrict__ ci) {
    __shared__ float2 srow[8][224];
    __shared__ float2 sW[224];
    int tid = threadIdx.x;
    for (int i = tid; i < 224; i += 256) sW[i] = g_W224[i];
    __syncthreads();
    int warp = tid >> 5, t = tid & 31;
    int rid = blockIdx.x * 8 + warp;                 // < 53760
    int c = rid / (Dd * Hd);
    int r2 = rid - c * (Dd * Hd);
    int h = r2 % Hd;
    const float2* prow = g_p + r2 * Wd;              // (d*H+h)*W
    const float* crr = cr + (c * Hd + h) * Wd;
    const float* cii = ci + (c * Hd + h) * Wd;
    float2 a[7];
    #pragma unroll
    for (int n1 = 0; n1 < 7; n1++) {
        int idx = n1 * 32 + t;
        float2 p = prow[idx];
        float2 co = make_float2(crr[idx], cii[idx]);
        a[n1] = cmulf(p, co);
    }
    float2 out[7];
    fft224_warp<false>(srow[warp], sW, t, a, out);
    #pragma unroll
    for (int k1 = 0; k1 < 7; k1++) srow[warp][7 * t + k1] = out[k1];
    __syncwarp();
    float2* orow = g_scr + (size_t)rid * Wd;
    for (int j = t; j < 224; j += 32) orow[j] = srow[warp][j];
}

// -------- length-448 FFT pieces. n = 64*n1 + n2, k = 7*k2 + k1. 16 threads/column. --------
template<bool INV>
__device__ __forceinline__ void fft448_stage1(float2* tile, const float2* sW, int g, int s) {
    #pragma unroll
    for (int r = 0; r < 4; r++) {
        int n2 = s + 16 * r;
        float2 a[7];
        #pragma unroll
        for (int n1 = 0; n1 < 7; n1++) a[n1] = tile[(n1 * 64 + n2) * 16 + g];
        #pragma unroll
        for (int k1 = 0; k1 < 7; k1++) {
            float2 acc = make_float2(0.f, 0.f);
            #pragma unroll
            for (int n1 = 0; n1 < 7; n1++) {
                float2 w = sW[64 * ((n1 * k1) % 7)];
                if (INV) w.y = -w.y;
                cmadd(acc, a[n1], w);
            }
            float2 tw = sW[n2 * k1];                 // <= 378 < 448
            if (INV) tw.y = -tw.y;
            tile[(k1 * 64 + n2) * 16 + g] = cmulf(acc, tw);
        }
    }
}
template<bool INV>
__device__ __forceinline__ void fft448_stage2(const float2* tile, const float2* sW, int g, int s,
                                              float2 acc[4][7]) {
    #pragma unroll
    for (int j = 0; j < 4; j++)
        #pragma unroll
        for (int k1 = 0; k1 < 7; k1++) acc[j][k1] = make_float2(0.f, 0.f);
    for (int n2 = 0; n2 < 64; n2++) {
        float2 x7[7];
        #pragma unroll
        for (int k1 = 0; k1 < 7; k1++) x7[k1] = tile[(k1 * 64 + n2) * 16 + g];
        #pragma unroll
        for (int j = 0; j < 4; j++) {
            int k2 = 4 * s + j;
            float2 w = sW[7 * ((n2 * k2) & 63)];
            if (INV) w.y = -w.y;
            #pragma unroll
            for (int k1 = 0; k1 < 7; k1++) cmadd(acc[j][k1], x7[k1], w);
        }
    }
}

// -------- K2: column FFT-448 + mask*(1/HW) + column IFFT-448, fused per 16-column tile --------
__global__ __launch_bounds__(256) void k_colfft(const int* __restrict__ mask) {
    extern __shared__ float2 sh[];                   // tile[448*16] ++ W448[448]
    float2* tile = sh;
    float2* sW = sh + 448 * 16;
    int tid = threadIdx.x;
    for (int i = tid; i < 448; i += 256) sW[i] = g_W448[i];
    int wt = blockIdx.x % 14;
    int cd = blockIdx.x / 14;                        // c*D + d
    int w0 = wt * 16;
    float2* gbase = g_scr + (size_t)cd * HW;
    int g = tid & 15, s = tid >> 4;                  // column lane, row group
    __syncthreads();
    // load tile (coalesced per half-warp)
    for (int i = 0; i < 28; i++) {
        int h = s + 16 * i;
        tile[h * 16 + g] = gbase[h * Wd + w0 + g];
    }
    __syncthreads();
    fft448_stage1<false>(tile, sW, g, s);
    __syncthreads();
    float2 acc[4][7];
    fft448_stage2<false>(tile, sW, g, s, acc);
    __syncthreads();
    // mask * (1/HW), write k-space back to tile (natural k order)
    #pragma unroll
    for (int j = 0; j < 4; j++) {
        int k2 = 4 * s + j;
        #pragma unroll
        for (int k1 = 0; k1 < 7; k1++) {
            int k = 7 * k2 + k1;
            float mv = mask[k * Wd + w0 + g] ? INV_HW : 0.f;
            float2 v = acc[j][k1];
            tile[k * 16 + g] = make_float2(v.x * mv, v.y * mv);
        }
    }
    __syncthreads();
    fft448_stage1<true>(tile, sW, g, s);
    __syncthreads();
    fft448_stage2<true>(tile, sW, g, s, acc);
    // store straight from registers (rows k = 7*k2+k1, column w0+g)
    #pragma unroll
    for (int j = 0; j < 4; j++) {
        int k2 = 4 * s + j;
        #pragma unroll
        for (int k1 = 0; k1 < 7; k1++)
            gbase[(7 * k2 + k1) * Wd + w0 + g] = acc[j][k1];
    }
}

// -------- K3: inverse row FFTs + conj-coil combine over coils + q = acc + mu*p; partial q.conj(p)
__global__ __launch_bounds__(256) void k_rowfft_inv(const float* __restrict__ cr,
                                                    const float* __restrict__ ci,
                                                    const float* __restrict__ miu) {
    __shared__ float2 srow[8][224];
    __shared__ float2 sprow[8][224];
    __shared__ float2 sW[224];
    int tid = threadIdx.x;
    for (int i = tid; i < 224; i += 256) sW[i] = g_W224[i];
    __syncthreads();
    int warp = tid >> 5, t = tid & 31;
    int rid = blockIdx.x * 8 + warp;                 // < 5376 = D*H
    int h = rid % Hd;
    const float2* prow = g_p + (size_t)rid * Wd;
    for (int j = t; j < 224; j += 32) sprow[warp][j] = prow[j];
    __syncwarp();
    float2 accq[7];
    #pragma unroll
    for (int k1 = 0; k1 < 7; k1++) accq[k1] = make_float2(0.f, 0.f);
    for (int c = 0; c < Cd; c++) {
        const float2* srcrow = g_scr + ((size_t)c * DHW + (size_t)rid * Wd);
        float2 a[7];
        #pragma unroll
        for (int n1 = 0; n1 < 7; n1++) a[n1] = srcrow[n1 * 32 + t];
        float2 out[7];
        fft224_warp<true>(srow[warp], sW, t, a, out);
        const float* crr = cr + (c * Hd + h) * Wd;
        const float* cii = ci + (c * Hd + h) * Wd;
        #pragma unroll
        for (int k1 = 0; k1 < 7; k1++) {
            int x = 7 * t + k1;
            float2 co = make_float2(crr[x], -cii[x]);   // conj(coil)
            cmadd(accq[k1], out[k1], co);
        }
    }
    float mu = fabsf(miu[0]);
    float2 qp = make_float2(0.f, 0.f);
    #pragma unroll
    for (int k1 = 0; k1 < 7; k1++) {
        int x = 7 * t + k1;
        float2 p = sprow[warp][x];
        float2 q = make_float2(fmaf(mu, p.x, accq[k1].x), fmaf(mu, p.y, accq[k1].y));
        accq[k1] = q;
        // qp += q * conj(p)
        qp.x += q.x * p.x + q.y * p.y;
        qp.y += q.y * p.x - q.x * p.y;
    }
    __syncwarp();
    #pragma unroll
    for (int k1 = 0; k1 < 7; k1++) srow[warp][7 * t + k1] = accq[k1];
    __syncwarp();
    float2* qrow = g_q + (size_t)rid * Wd;
    for (int j = t; j < 224; j += 32) qrow[j] = srow[warp][j];
    qp = blockReduceC(qp);
    if (tid == 0) g_qp_part[blockIdx.x] = qp;
}

// -------- alpha = rr / sum(q conj p) --------
__global__ void k_alpha(int it) {
    float2 v = make_float2(0.f, 0.f);
    for (int i = threadIdx.x; i < NB_Q; i += 256) {
        v.x += g_qp_part[i].x; v.y += g_qp_part[i].y;
    }
    v = blockReduceC(v);
    if (threadIdx.x == 0) {
        float rr = g_rr[it];
        float den = v.x * v.x + v.y * v.y;
        g_alpha[it] = make_float2(rr * v.x / den, -rr * v.y / den);
    }
}

// -------- b += alpha*p ; r -= alpha*q ; partial ||r||^2 --------
__global__ __launch_bounds__(256) void k_update_br(int it) {
    float2 al = g_alpha[it];
    float rr = 0.f;
    for (int n = blockIdx.x * 256 + threadIdx.x; n < DHW; n += NB_EW * 256) {
        float2 p = g_p[n], q = g_q[n], r = g_r[n], b = g_b[n];
        b.x += al.x * p.x - al.y * p.y;
        b.y += al.x * p.y + al.y * p.x;
        r.x -= al.x * q.x - al.y * q.y;
        r.y -= al.x * q.y + al.y * q.x;
        g_b[n] = b; g_r[n] = r;
        rr = fmaf(r.x, r.x, fmaf(r.y, r.y, rr));
    }
    rr = blockReduceF(rr);
    if (threadIdx.x == 0) g_rr_part[blockIdx.x] = rr;
}

__global__ void k_beta(int it) {
    float v = 0.f;
    for (int i = threadIdx.x; i < NB_EW; i += 256) v += g_rr_part[i];
    v = blockReduceF(v);
    if (threadIdx.x == 0) {
        g_rr[it + 1] = v;
        g_beta[it] = v / g_rr[it];
    }
}

// -------- p = r + beta*p --------
__global__ __launch_bounds__(256) void k_update_p(int it) {
    float be = g_beta[it];
    for (int n = blockIdx.x * 256 + threadIdx.x; n < DHW; n += NB_EW * 256) {
        float2 r = g_r[n], p = g_p[n];
        g_p[n] = make_float2(fmaf(be, p.x, r.x), fmaf(be, p.y, r.y));
    }
}

// -------- output: undo sign checkerboard --------
__global__ __launch_bounds__(256) void k_out(float* __restrict__ out) {
    for (int n = blockIdx.x * 256 + threadIdx.x; n < DHW; n += NB_EW * 256) {
        int w = n % Wd;
        int h = (n / Wd) % Hd;
        float s = ((h + w) & 1) ? -1.f : 1.f;
        float2 b = g_b[n];
        out[n] = s * b.x;
        out[DHW + n] = s * b.y;
    }
}

extern "C" void kernel_launch(void* const* d_in, const int* in_sizes, int n_in,
                              void* d_out, int out_size) {
    const float* z    = (const float*)d_in[0];
    const float* zf   = (const float*)d_in[1];
    const float* cr   = (const float*)d_in[2];
    const float* ci   = (const float*)d_in[3];
    const int*   mask = (const int*)d_in[4];
    const float* miu  = (const float*)d_in[5];
    float* out = (float*)d_out;

    const int k2_shmem = 448 * 16 * (int)sizeof(float2) + 448 * (int)sizeof(float2); // 60928
    cudaFuncSetAttribute(k_colfft, cudaFuncAttributeMaxDynamicSharedMemorySize, k2_shmem);

    k_twiddle<<<1, 448>>>();
    k_init<<<NB_EW, 256>>>(z, zf, miu);
    k_sum_rr0<<<1, 256>>>();
    for (int it = 0; it < 5; ++it) {
        k_rowfft_fwd<<<6720, 256>>>(cr, ci);           // C*D*H/8
        k_colfft<<<1680, 256, k2_shmem>>>(mask);       // C*D*(W/16)
        k_rowfft_inv<<<NB_Q, 256>>>(cr, ci, miu);      // D*H/8
        k_alpha<<<1, 256>>>(it);
        k_update_br<<<NB_EW, 256>>>(it);
        k_beta<<<1, 256>>>(it);
        k_update_p<<<NB_EW, 256>>>(it);
    }
    k_out<<<NB_EW, 256>>>(out);
}

// round 2
// speedup vs baseline: 1.2610x; 1.2610x over previous
#include <cuda_runtime.h>
#include <math.h>

// Problem dims
#define Hd   448
#define Wd   224
#define Dd   12
#define Cd   10
#define HW   100352          // 448*224
#define DHW  1204224         // 12*HW
#define CDHW 12042240        // 10*DHW
#define INV_HW (1.0f/100352.0f)
#define NB_EW 1024           // blocks for elementwise+reduce kernels
#define NB_Q  672            // blocks for K3 (D*H/8)
#define PI_D 3.14159265358979323846
#define TSTR 17              // padded tile stride (float2) for K2

// -------- device scratch (static __device__ arrays: allocation-free) --------
__device__ float2 g_scr[CDHW];     // coil-expanded slices [c][d][h][w]  (96 MB)
__device__ float2 g_p[DHW];
__device__ float2 g_r[DHW];
__device__ float2 g_b[DHW];
__device__ float2 g_q[DHW];
__device__ float2 g_W224[224];
__device__ float2 g_W448[448];
__device__ float  g_rr[8];
__device__ float2 g_alpha[8];
__device__ float  g_beta[8];
__device__ float2 g_qp_part[NB_Q];
__device__ float  g_rr_part[NB_EW];

// -------- complex helpers --------
__device__ __forceinline__ float2 cmulf(float2 a, float2 b) {
    return make_float2(a.x*b.x - a.y*b.y, a.x*b.y + a.y*b.x);
}
__device__ __forceinline__ void cmadd(float2& acc, float2 a, float2 b) {
    acc.x = fmaf(a.x, b.x, fmaf(-a.y, b.y, acc.x));
    acc.y = fmaf(a.x, b.y, fmaf( a.y, b.x, acc.y));
}

__device__ __forceinline__ int bitrev5(int t) {
    return ((t & 1) << 4) | ((t & 2) << 2) | (t & 4) | ((t & 8) >> 2) | ((t & 16) >> 4);
}

// radix-2 DIF butterfly across lanes (twiddle pre-conjugated by caller for inverse)
__device__ __forceinline__ void bfly(float2& v, int t, int m, float2 tw) {
    float2 o;
    o.x = __shfl_xor_sync(0xffffffffu, v.x, m);
    o.y = __shfl_xor_sync(0xffffffffu, v.y, m);
    float2 sum = make_float2(v.x + o.x, v.y + o.y);
    float2 dif = make_float2(o.x - v.x, o.y - v.y);
    float2 dm  = cmulf(dif, tw);
    v = (t & m) ? dm : sum;
}

// -------- deterministic block reductions --------
__device__ __forceinline__ float blockReduceF(float v) {
    __shared__ float red[8];
    int lane = threadIdx.x & 31, wp = threadIdx.x >> 5;
    #pragma unroll
    for (int o = 16; o > 0; o >>= 1) v += __shfl_down_sync(0xffffffffu, v, o);
    if (lane == 0) red[wp] = v;
    __syncthreads();
    if (wp == 0) {
        v = (lane < 8) ? red[lane] : 0.f;
        #pragma unroll
        for (int o = 4; o > 0; o >>= 1) v += __shfl_down_sync(0xffffffffu, v, o);
    }
    return v;   // valid on thread 0
}
__device__ __forceinline__ float2 blockReduceC(float2 v) {
    __shared__ float2 redc[8];
    int lane = threadIdx.x & 31, wp = threadIdx.x >> 5;
    #pragma unroll
    for (int o = 16; o > 0; o >>= 1) {
        v.x += __shfl_down_sync(0xffffffffu, v.x, o);
        v.y += __shfl_down_sync(0xffffffffu, v.y, o);
    }
    if (lane == 0) redc[wp] = v;
    __syncthreads();
    if (wp == 0) {
        v = (lane < 8) ? redc[lane] : make_float2(0.f, 0.f);
        #pragma unroll
        for (int o = 4; o > 0; o >>= 1) {
            v.x += __shfl_down_sync(0xffffffffu, v.x, o);
            v.y += __shfl_down_sync(0xffffffffu, v.y, o);
        }
    }
    return v;
}

// -------- twiddle init --------
__global__ void k_twiddle() {
    int i = threadIdx.x;
    if (i < 224) {
        double a = -2.0 * PI_D * (double)i / 224.0;
        g_W224[i] = make_float2((float)cos(a), (float)sin(a));
    }
    if (i < 448) {
        double a = -2.0 * PI_D * (double)i / 448.0;
        g_W448[i] = make_float2((float)cos(a), (float)sin(a));
    }
}

// -------- 224-pt FFT per warp: radix-7 (lane-local) then shuffle FFT-32 across lanes.
// Input: a[n1] = x[32*n1 + t].  Output: out[k1] = X[7*bitrev5(t) + k1].
template<bool INV>
__device__ __forceinline__ void fft224_reg(const float2* sW, int t,
        float2 tw16, float2 tw8, float2 tw4, float2 tw2,
        const float2 a[7], float2 out[7]) {
    #pragma unroll
    for (int k1 = 0; k1 < 7; k1++) {
        float2 acc = make_float2(0.f, 0.f);
        #pragma unroll
        for (int n1 = 0; n1 < 7; n1++) {
            float2 w = sW[32 * ((n1 * k1) % 7)];
            if (INV) w.y = -w.y;
            cmadd(acc, a[n1], w);
        }
        float2 twt = sW[t * k1];          // t*k1 <= 186 < 224
        if (INV) twt.y = -twt.y;
        float2 v = cmulf(acc, twt);
        bfly(v, t, 16, tw16);
        bfly(v, t,  8, tw8);
        bfly(v, t,  4, tw4);
        bfly(v, t,  2, tw2);
        float2 o;
        o.x = __shfl_xor_sync(0xffffffffu, v.x, 1);
        o.y = __shfl_xor_sync(0xffffffffu, v.y, 1);
        v = (t & 1) ? make_float2(o.x - v.x, o.y - v.y)
                    : make_float2(v.x + o.x, v.y + o.y);
        out[k1] = v;
    }
}

// -------- K0: p = s*(zf + mu*z); r = p; b = 0; partial ||p||^2 --------
__global__ __launch_bounds__(256) void k_init(const float* __restrict__ z,
                                              const float* __restrict__ zf,
                                              const float* __restrict__ miu) {
    float mu = fabsf(miu[0]);
    float rr = 0.f;
    for (int n = blockIdx.x * 256 + threadIdx.x; n < DHW; n += NB_EW * 256) {
        int w = n % Wd;
        int h = (n / Wd) % Hd;
        float s = ((h + w) & 1) ? -1.f : 1.f;
        float pr = s * (zf[n] + mu * z[n]);
        float pi = s * (zf[DHW + n] + mu * z[DHW + n]);
        float2 p = make_float2(pr, pi);
        g_p[n] = p; g_r[n] = p; g_b[n] = make_float2(0.f, 0.f);
        rr = fmaf(pr, pr, fmaf(pi, pi, rr));
    }
    rr = blockReduceF(rr);
    if (threadIdx.x == 0) g_rr_part[blockIdx.x] = rr;
}

__global__ void k_sum_rr0() {
    float v = 0.f;
    for (int i = threadIdx.x; i < NB_EW; i += 256) v += g_rr_part[i];
    v = blockReduceF(v);
    if (threadIdx.x == 0) g_rr[0] = v;
}

// -------- K1: forward row FFTs with coil expand. 8 warps/CTA, 1 warp per row --------
__global__ __launch_bounds__(256) void k_rowfft_fwd(const float* __restrict__ cr,
                                                    const float* __restrict__ ci) {
    __shared__ float2 srow[8][224];
    __shared__ float2 sW[224];
    int tid = threadIdx.x;
    for (int i = tid; i < 224; i += 256) sW[i] = g_W224[i];
    __syncthreads();
    int warp = tid >> 5, t = tid & 31;
    float2 tw16 = sW[7  * (t & 15)];
    float2 tw8  = sW[14 * (t & 7)];
    float2 tw4  = sW[28 * (t & 3)];
    float2 tw2  = sW[56 * (t & 1)];
    int rid = blockIdx.x * 8 + warp;                 // < 53760
    int c = rid / (Dd * Hd);
    int r2 = rid - c * (Dd * Hd);
    int h = r2 % Hd;
    const float2* prow = g_p + r2 * Wd;
    const float* crr = cr + (c * Hd + h) * Wd;
    const float* cii = ci + (c * Hd + h) * Wd;
    float2 a[7];
    #pragma unroll
    for (int n1 = 0; n1 < 7; n1++) {
        int idx = n1 * 32 + t;
        float2 p = prow[idx];
        float2 co = make_float2(crr[idx], cii[idx]);
        a[n1] = cmulf(p, co);
    }
    float2 out[7];
    fft224_reg<false>(sW, t, tw16, tw8, tw4, tw2, a, out);
    int rt = bitrev5(t);
    #pragma unroll
    for (int k1 = 0; k1 < 7; k1++) srow[warp][7 * rt + k1] = out[k1];
    __syncwarp();
    float2* orow = g_scr + (size_t)rid * Wd;
    for (int j = t; j < 224; j += 32) orow[j] = srow[warp][j];
}

// -------- 448-pt column FFT: radix-7 stage + (4x16) CT for the 64-pt part.
// Thread layout: g = column lane (0..15), s = row group (0..15).
// Output: out[k1][km] = X[7*(4*s+km) + k1] for column g.
// zbuf aliases tile (all tile reads complete before zbuf writes; sync-guarded).
template<bool INV>
__device__ __forceinline__ void col_fft448(float2* tile, float4* zbuf,
                                           const float2* sW, int g, int s,
                                           float2 out[7][4]) {
    float2 z[7][4];
    #pragma unroll
    for (int r = 0; r < 4; r++) {
        int n2 = 16 * r + s;
        float2 a[7];
        #pragma unroll
        for (int n1 = 0; n1 < 7; n1++) a[n1] = tile[(n1 * 64 + n2) * TSTR + g];
        #pragma unroll
        for (int k1 = 0; k1 < 7; k1++) {
            float2 acc = make_float2(0.f, 0.f);
            #pragma unroll
            for (int n1 = 0; n1 < 7; n1++) {
                float2 w = sW[64 * ((n1 * k1) % 7)];
                if (INV) w.y = -w.y;
                cmadd(acc, a[n1], w);
            }
            float2 tw = sW[n2 * k1];                 // <= 378 < 448
            if (INV) tw.y = -tw.y;
            z[k1][r] = cmulf(acc, tw);
        }
    }
    // radix-4 over r (trivial twiddles) + twiddle w64^{s*km}
    #pragma unroll
    for (int k1 = 0; k1 < 7; k1++) {
        float2 x0 = z[k1][0], x1 = z[k1][1], x2 = z[k1][2], x3 = z[k1][3];
        float2 t0 = make_float2(x0.x + x2.x, x0.y + x2.y);
        float2 t2 = make_float2(x0.x - x2.x, x0.y - x2.y);
        float2 t1 = make_float2(x1.x + x3.x, x1.y + x3.y);
        float2 t3 = make_float2(x1.x - x3.x, x1.y - x3.y);
        float2 it3 = INV ? make_float2(-t3.y, t3.x) : make_float2(t3.y, -t3.x);  // ±i*t3
        float2 y0 = make_float2(t0.x + t1.x, t0.y + t1.y);
        float2 y2 = make_float2(t0.x - t1.x, t0.y - t1.y);
        float2 y1 = make_float2(t2.x + it3.x, t2.y + it3.y);
        float2 y3 = make_float2(t2.x - it3.x, t2.y - it3.y);
        float2 w1 = sW[7  * s]; if (INV) w1.y = -w1.y;
        float2 w2 = sW[14 * s]; if (INV) w2.y = -w2.y;
        float2 w3 = sW[21 * s]; if (INV) w3.y = -w3.y;
        z[k1][0] = y0;
        z[k1][1] = cmulf(y1, w1);
        z[k1][2] = cmulf(y2, w2);
        z[k1][3] = cmulf(y3, w3);
    }
    __syncthreads();   // all tile reads done; zbuf may now overwrite tile bytes
    #pragma unroll
    for (int k1 = 0; k1 < 7; k1++) {
        zbuf[((k1 * 16 + s) * 2 + 0) * 16 + g] =
            make_float4(z[k1][0].x, z[k1][0].y, z[k1][1].x, z[k1][1].y);
        zbuf[((k1 * 16 + s) * 2 + 1) * 16 + g] =
            make_float4(z[k1][2].x, z[k1][2].y, z[k1][3].x, z[k1][3].y);
    }
    __syncthreads();
    #pragma unroll
    for (int k1 = 0; k1 < 7; k1++)
        #pragma unroll
        for (int km = 0; km < 4; km++) out[k1][km] = make_float2(0.f, 0.f);
    // cross-thread 16-pt DFT: out index k_c = s
    for (int sp = 0; sp < 16; sp++) {
        float2 w = sW[28 * ((s * sp) & 15)];
        if (INV) w.y = -w.y;
        #pragma unroll
        for (int k1 = 0; k1 < 7; k1++) {
            float4 v0 = zbuf[((k1 * 16 + sp) * 2 + 0) * 16 + g];
            float4 v1 = zbuf[((k1 * 16 + sp) * 2 + 1) * 16 + g];
            cmadd(out[k1][0], make_float2(v0.x, v0.y), w);
            cmadd(out[k1][1], make_float2(v0.z, v0.w), w);
            cmadd(out[k1][2], make_float2(v1.x, v1.y), w);
            cmadd(out[k1][3], make_float2(v1.z, v1.w), w);
        }
    }
}

// -------- K2: column FFT-448 + mask*(1/HW) + column IFFT-448, fused per 16-column tile
__global__ __launch_bounds__(256) void k_colfft(const int* __restrict__ mask) {
    extern __shared__ float2 sh[];                   // tile[448*TSTR] ++ W448[448]
    float2* tile = sh;
    float2* sW = sh + 448 * TSTR;
    float4* zbuf = (float4*)sh;                      // aliases tile (57344B < tile)
    int tid = threadIdx.x;
    for (int i = tid; i < 448; i += 256) sW[i] = g_W448[i];
    int wt = blockIdx.x % 14;
    int cd = blockIdx.x / 14;                        // c*D + d
    int w0 = wt * 16;
    float2* gbase = g_scr + (size_t)cd * HW;
    int g = tid & 15, s = tid >> 4;                  // column lane, row group
    __syncthreads();
    for (int i = 0; i < 28; i++) {
        int h = s + 16 * i;
        tile[h * TSTR + g] = gbase[h * Wd + w0 + g];
    }
    __syncthreads();
    float2 out[7][4];
    col_fft448<false>(tile, zbuf, sW, g, s, out);
    __syncthreads();                                 // zbuf reads done
    #pragma unroll
    for (int km = 0; km < 4; km++)
        #pragma unroll
        for (int k1 = 0; k1 < 7; k1++) {
            int k = 7 * (4 * s + km) + k1;
            float mv = mask[k * Wd + w0 + g] ? INV_HW : 0.f;
            tile[k * TSTR + g] = make_float2(out[k1][km].x * mv, out[k1][km].y * mv);
        }
    __syncthreads();
    col_fft448<true>(tile, zbuf, sW, g, s, out);
    #pragma unroll
    for (int km = 0; km < 4; km++)
        #pragma unroll
        for (int k1 = 0; k1 < 7; k1++)
            gbase[(7 * (4 * s + km) + k1) * Wd + w0 + g] = out[k1][km];
}

// -------- K3: inverse row FFTs + conj-coil combine + q = acc + mu*p; partial q.conj(p)
__global__ __launch_bounds__(256) void k_rowfft_inv(const float* __restrict__ cr,
                                                    const float* __restrict__ ci,
                                                    const float* __restrict__ miu) {
    __shared__ float2 srow[8][224];
    __shared__ float2 sprow[8][224];
    __shared__ float2 sW[224];
    int tid = threadIdx.x;
    for (int i = tid; i < 224; i += 256) sW[i] = g_W224[i];
    __syncthreads();
    int warp = tid >> 5, t = tid & 31;
    float2 tw16 = sW[7  * (t & 15)]; tw16.y = -tw16.y;
    float2 tw8  = sW[14 * (t & 7)];  tw8.y  = -tw8.y;
    float2 tw4  = sW[28 * (t & 3)];  tw4.y  = -tw4.y;
    float2 tw2  = sW[56 * (t & 1)];  tw2.y  = -tw2.y;
    int rid = blockIdx.x * 8 + warp;                 // < 5376 = D*H
    int h = rid % Hd;
    const float2* prow = g_p + (size_t)rid * Wd;
    for (int j = t; j < 224; j += 32) sprow[warp][j] = prow[j];
    __syncwarp();
    int rt = bitrev5(t);
    float2 accq[7];
    #pragma unroll
    for (int k1 = 0; k1 < 7; k1++) accq[k1] = make_float2(0.f, 0.f);
    for (int c = 0; c < Cd; c++) {
        const float2* srcrow = g_scr + ((size_t)c * DHW + (size_t)rid * Wd);
        float2 a[7];
        #pragma unroll
        for (int n1 = 0; n1 < 7; n1++) a[n1] = srcrow[n1 * 32 + t];
        float2 out[7];
        fft224_reg<true>(sW, t, tw16, tw8, tw4, tw2, a, out);
        const float* crr = cr + (c * Hd + h) * Wd;
        const float* cii = ci + (c * Hd + h) * Wd;
        #pragma unroll
        for (int k1 = 0; k1 < 7; k1++) {
            int x = 7 * rt + k1;
            float2 co = make_float2(crr[x], -cii[x]);   // conj(coil)
            cmadd(accq[k1], out[k1], co);
        }
    }
    float mu = fabsf(miu[0]);
    float2 qp = make_float2(0.f, 0.f);
    #pragma unroll
    for (int k1 = 0; k1 < 7; k1++) {
        int x = 7 * rt + k1;
        float2 p = sprow[warp][x];
        float2 q = make_float2(fmaf(mu, p.x, accq[k1].x), fmaf(mu, p.y, accq[k1].y));
        accq[k1] = q;
        qp.x += q.x * p.x + q.y * p.y;      // q * conj(p)
        qp.y += q.y * p.x - q.x * p.y;
    }
    __syncwarp();
    #pragma unroll
    for (int k1 = 0; k1 < 7; k1++) srow[warp][7 * rt + k1] = accq[k1];
    __syncwarp();
    float2* qrow = g_q + (size_t)rid * Wd;
    for (int j = t; j < 224; j += 32) qrow[j] = srow[warp][j];
    qp = blockReduceC(qp);
    if (tid == 0) g_qp_part[blockIdx.x] = qp;
}

// -------- alpha = rr / sum(q conj p) --------
__global__ void k_alpha(int it) {
    float2 v = make_float2(0.f, 0.f);
    for (int i = threadIdx.x; i < NB_Q; i += 256) {
        v.x += g_qp_part[i].x; v.y += g_qp_part[i].y;
    }
    v = blockReduceC(v);
    if (threadIdx.x == 0) {
        float rr = g_rr[it];
        float den = v.x * v.x + v.y * v.y;
        g_alpha[it] = make_float2(rr * v.x / den, -rr * v.y / den);
    }
}

// -------- b += alpha*p ; r -= alpha*q ; partial ||r||^2 --------
__global__ __launch_bounds__(256) void k_update_br(int it) {
    float2 al = g_alpha[it];
    float rr = 0.f;
    for (int n = blockIdx.x * 256 + threadIdx.x; n < DHW; n += NB_EW * 256) {
        float2 p = g_p[n], q = g_q[n], r = g_r[n], b = g_b[n];
        b.x += al.x * p.x - al.y * p.y;
        b.y += al.x * p.y + al.y * p.x;
        r.x -= al.x * q.x - al.y * q.y;
        r.y -= al.x * q.y + al.y * q.x;
        g_b[n] = b; g_r[n] = r;
        rr = fmaf(r.x, r.x, fmaf(r.y, r.y, rr));
    }
    rr = blockReduceF(rr);
    if (threadIdx.x == 0) g_rr_part[blockIdx.x] = rr;
}

__global__ void k_beta(int it) {
    float v = 0.f;
    for (int i = threadIdx.x; i < NB_EW; i += 256) v += g_rr_part[i];
    v = blockReduceF(v);
    if (threadIdx.x == 0) {
        g_rr[it + 1] = v;
        g_beta[it] = v / g_rr[it];
    }
}

// -------- p = r + beta*p --------
__global__ __launch_bounds__(256) void k_update_p(int it) {
    float be = g_beta[it];
    for (int n = blockIdx.x * 256 + threadIdx.x; n < DHW; n += NB_EW * 256) {
        float2 r = g_r[n], p = g_p[n];
        g_p[n] = make_float2(fmaf(be, p.x, r.x), fmaf(be, p.y, r.y));
    }
}

// -------- output: undo sign checkerboard --------
__global__ __launch_bounds__(256) void k_out(float* __restrict__ out) {
    for (int n = blockIdx.x * 256 + threadIdx.x; n < DHW; n += NB_EW * 256) {
        int w = n % Wd;
        int h = (n / Wd) % Hd;
        float s = ((h + w) & 1) ? -1.f : 1.f;
        float2 b = g_b[n];
        out[n] = s * b.x;
        out[DHW + n] = s * b.y;
    }
}

extern "C" void kernel_launch(void* const* d_in, const int* in_sizes, int n_in,
                              void* d_out, int out_size) {
    const float* z    = (const float*)d_in[0];
    const float* zf   = (const float*)d_in[1];
    const float* cr   = (const float*)d_in[2];
    const float* ci   = (const float*)d_in[3];
    const int*   mask = (const int*)d_in[4];
    const float* miu  = (const float*)d_in[5];
    float* out = (float*)d_out;

    const int k2_shmem = 448 * TSTR * (int)sizeof(float2) + 448 * (int)sizeof(float2); // 64512
    cudaFuncSetAttribute(k_colfft, cudaFuncAttributeMaxDynamicSharedMemorySize, k2_shmem);

    k_twiddle<<<1, 448>>>();
    k_init<<<NB_EW, 256>>>(z, zf, miu);
    k_sum_rr0<<<1, 256>>>();
    for (int it = 0; it < 5; ++it) {
        k_rowfft_fwd<<<6720, 256>>>(cr, ci);           // C*D*H/8
        k_colfft<<<1680, 256, k2_shmem>>>(mask);       // C*D*(W/16)
        k_rowfft_inv<<<NB_Q, 256>>>(cr, ci, miu);      // D*H/8
        k_alpha<<<1, 256>>>(it);
        k_update_br<<<NB_EW, 256>>>(it);
        k_beta<<<1, 256>>>(it);
        k_update_p<<<NB_EW, 256>>>(it);
    }
    k_out<<<NB_EW, 256>>>(out);
}

// round 3
// speedup vs baseline: 2.1167x; 1.6786x over previous
#include <cuda_runtime.h>
#include <math.h>

// Problem dims
#define Hd   448
#define Wd   224
#define Dd   12
#define Cd   10
#define HW   100352          // 448*224
#define DHW  1204224         // 12*HW
#define CDHW 12042240        // 10*DHW
#define INV_HW (1.0f/100352.0f)
#define NB_EW 1024           // blocks for elementwise+reduce kernels
#define NB_Q  672            // blocks for K3 (D*H/8)
#define PI_D 3.14159265358979323846
#define TSTR 17              // padded tile stride (float2) for K2

// -------- device scratch (static __device__ arrays: allocation-free) --------
__device__ float2 g_scr[CDHW];     // coil-expanded slices [c][d][h][w]  (96 MB)
__device__ float2 g_p[DHW];
__device__ float2 g_r[DHW];
__device__ float2 g_b[DHW];
__device__ float2 g_q[DHW];
__device__ float2 g_W224[224];
__device__ float2 g_W448[448];
__device__ float  g_rr[8];
__device__ float2 g_alpha[8];
__device__ float  g_beta[8];
__device__ float2 g_qp_part[NB_Q];
__device__ float  g_rr_part[NB_EW];

// -------- complex helpers --------
__device__ __forceinline__ float2 cmulf(float2 a, float2 b) {
    return make_float2(a.x*b.x - a.y*b.y, a.x*b.y + a.y*b.x);
}
__device__ __forceinline__ void cmadd(float2& acc, float2 a, float2 b) {
    acc.x = fmaf(a.x, b.x, fmaf(-a.y, b.y, acc.x));
    acc.y = fmaf(a.x, b.y, fmaf( a.y, b.x, acc.y));
}
__device__ __forceinline__ float2 cadd(float2 a, float2 b){ return make_float2(a.x+b.x, a.y+b.y); }
__device__ __forceinline__ float2 csub(float2 a, float2 b){ return make_float2(a.x-b.x, a.y-b.y); }

__device__ __forceinline__ int bitrev5(int t) {
    return ((t & 1) << 4) | ((t & 2) << 2) | (t & 4) | ((t & 8) >> 2) | ((t & 16) >> 4);
}

// multiply by W4^m (forward W4 = -i); m in [0,4)
template<bool INV>
__device__ __forceinline__ float2 w4rot(float2 z, int m) {
    bool half = (m & 1) != 0;
    float rx = half ? (INV ? -z.y : z.y) : z.x;
    float ry = half ? (INV ?  z.x : -z.x) : z.y;
    if (m & 2) { rx = -rx; ry = -ry; }
    return make_float2(rx, ry);
}

// -------- symmetric DFT-7 (real-immediate coefficients) --------
template<bool INV>
__device__ __forceinline__ void dft7(const float2 x[7], float2 X[7]) {
    const float C1f =  0.62348980185873359f;   // cos(2pi/7)
    const float C2f = -0.22252093395631440f;   // cos(4pi/7)
    const float C3f = -0.90096886790241915f;   // cos(6pi/7)
    const float S1f =  0.78183148246802981f;   // sin(2pi/7)
    const float S2f =  0.97492791218182360f;   // sin(4pi/7)
    const float S3f =  0.43388373911755812f;   // sin(6pi/7)
    float2 a1 = cadd(x[1], x[6]), b1 = csub(x[1], x[6]);
    float2 a2 = cadd(x[2], x[5]), b2 = csub(x[2], x[5]);
    float2 a3 = cadd(x[3], x[4]), b3 = csub(x[3], x[4]);
    X[0] = make_float2(x[0].x + a1.x + a2.x + a3.x,
                       x[0].y + a1.y + a2.y + a3.y);
    float2 u1, u2, u3, v1, v2, v3;
    u1.x = fmaf(C1f,a1.x, fmaf(C2f,a2.x, fmaf(C3f,a3.x, x[0].x)));
    u1.y = fmaf(C1f,a1.y, fmaf(C2f,a2.y, fmaf(C3f,a3.y, x[0].y)));
    u2.x = fmaf(C2f,a1.x, fmaf(C3f,a2.x, fmaf(C1f,a3.x, x[0].x)));
    u2.y = fmaf(C2f,a1.y, fmaf(C3f,a2.y, fmaf(C1f,a3.y, x[0].y)));
    u3.x = fmaf(C3f,a1.x, fmaf(C1f,a2.x, fmaf(C2f,a3.x, x[0].x)));
    u3.y = fmaf(C3f,a1.y, fmaf(C1f,a2.y, fmaf(C2f,a3.y, x[0].y)));
    v1.x = fmaf(S1f,b1.x, fmaf( S2f,b2.x,  S3f*b3.x));
    v1.y = fmaf(S1f,b1.y, fmaf( S2f,b2.y,  S3f*b3.y));
    v2.x = fmaf(S2f,b1.x, fmaf(-S3f,b2.x, -S1f*b3.x));
    v2.y = fmaf(S2f,b1.y, fmaf(-S3f,b2.y, -S1f*b3.y));
    v3.x = fmaf(S3f,b1.x, fmaf(-S1f,b2.x,  S2f*b3.x));
    v3.y = fmaf(S3f,b1.y, fmaf(-S1f,b2.y,  S2f*b3.y));
    if (!INV) {
        X[1] = make_float2(u1.x + v1.y, u1.y - v1.x);
        X[6] = make_float2(u1.x - v1.y, u1.y + v1.x);
        X[2] = make_float2(u2.x + v2.y, u2.y - v2.x);
        X[5] = make_float2(u2.x - v2.y, u2.y + v2.x);
        X[3] = make_float2(u3.x + v3.y, u3.y - v3.x);
        X[4] = make_float2(u3.x - v3.y, u3.y + v3.x);
    } else {
        X[1] = make_float2(u1.x - v1.y, u1.y + v1.x);
        X[6] = make_float2(u1.x + v1.y, u1.y - v1.x);
        X[2] = make_float2(u2.x - v2.y, u2.y + v2.x);
        X[5] = make_float2(u2.x + v2.y, u2.y - v2.x);
        X[3] = make_float2(u3.x - v3.y, u3.y + v3.x);
        X[4] = make_float2(u3.x + v3.y, u3.y - v3.x);
    }
}

// radix-2 DIF butterfly across lanes (twiddle pre-conjugated by caller for inverse)
__device__ __forceinline__ void bfly(float2& v, int t, int m, float2 tw) {
    float2 o;
    o.x = __shfl_xor_sync(0xffffffffu, v.x, m);
    o.y = __shfl_xor_sync(0xffffffffu, v.y, m);
    float2 sum = make_float2(v.x + o.x, v.y + o.y);
    float2 dif = make_float2(o.x - v.x, o.y - v.y);
    float2 dm  = cmulf(dif, tw);
    v = (t & m) ? dm : sum;
}

// -------- deterministic block reductions --------
__device__ __forceinline__ float blockReduceF(float v) {
    __shared__ float red[8];
    int lane = threadIdx.x & 31, wp = threadIdx.x >> 5;
    #pragma unroll
    for (int o = 16; o > 0; o >>= 1) v += __shfl_down_sync(0xffffffffu, v, o);
    if (lane == 0) red[wp] = v;
    __syncthreads();
    if (wp == 0) {
        v = (lane < 8) ? red[lane] : 0.f;
        #pragma unroll
        for (int o = 4; o > 0; o >>= 1) v += __shfl_down_sync(0xffffffffu, v, o);
    }
    return v;   // valid on thread 0
}
__device__ __forceinline__ float2 blockReduceC(float2 v) {
    __shared__ float2 redc[8];
    int lane = threadIdx.x & 31, wp = threadIdx.x >> 5;
    #pragma unroll
    for (int o = 16; o > 0; o >>= 1) {
        v.x += __shfl_down_sync(0xffffffffu, v.x, o);
        v.y += __shfl_down_sync(0xffffffffu, v.y, o);
    }
    if (lane == 0) redc[wp] = v;
    __syncthreads();
    if (wp == 0) {
        v = (lane < 8) ? redc[lane] : make_float2(0.f, 0.f);
        #pragma unroll
        for (int o = 4; o > 0; o >>= 1) {
            v.x += __shfl_down_sync(0xffffffffu, v.x, o);
            v.y += __shfl_down_sync(0xffffffffu, v.y, o);
        }
    }
    return v;
}

// -------- twiddle init --------
__global__ void k_twiddle() {
    int i = threadIdx.x;
    if (i < 224) {
        double a = -2.0 * PI_D * (double)i / 224.0;
        g_W224[i] = make_float2((float)cos(a), (float)sin(a));
    }
    if (i < 448) {
        double a = -2.0 * PI_D * (double)i / 448.0;
        g_W448[i] = make_float2((float)cos(a), (float)sin(a));
    }
}

// -------- 224-pt FFT per warp: symmetric radix-7 (lane-local) + shuffle FFT-32.
// Input: a[n1] = x[32*n1 + t].  Output: out[k1] = X[7*bitrev5(t) + k1].
template<bool INV>
__device__ __forceinline__ void fft224_reg(const float2* sW, int t,
        float2 tw16, float2 tw8, float2 tw4, float2 tw2,
        const float2 a[7], float2 out[7]) {
    float2 y[7];
    dft7<INV>(a, y);
    #pragma unroll
    for (int k1 = 0; k1 < 7; k1++) {
        float2 twt = sW[t * k1];          // t*k1 <= 186 < 224
        if (INV) twt.y = -twt.y;
        float2 v = cmulf(y[k1], twt);
        bfly(v, t, 16, tw16);
        bfly(v, t,  8, tw8);
        bfly(v, t,  4, tw4);
        bfly(v, t,  2, tw2);
        float2 o;
        o.x = __shfl_xor_sync(0xffffffffu, v.x, 1);
        o.y = __shfl_xor_sync(0xffffffffu, v.y, 1);
        v = (t & 1) ? make_float2(o.x - v.x, o.y - v.y)
                    : make_float2(v.x + o.x, v.y + o.y);
        out[k1] = v;
    }
}

// -------- K0: p = s*(zf + mu*z); r = p; b = 0; partial ||p||^2 --------
__global__ __launch_bounds__(256) void k_init(const float* __restrict__ z,
                                              const float* __restrict__ zf,
                                              const float* __restrict__ miu) {
    float mu = fabsf(miu[0]);
    float rr = 0.f;
    for (int n = blockIdx.x * 256 + threadIdx.x; n < DHW; n += NB_EW * 256) {
        int w = n % Wd;
        int h = (n / Wd) % Hd;
        float s = ((h + w) & 1) ? -1.f : 1.f;
        float pr = s * (zf[n] + mu * z[n]);
        float pi = s * (zf[DHW + n] + mu * z[DHW + n]);
        float2 p = make_float2(pr, pi);
        g_p[n] = p; g_r[n] = p; g_b[n] = make_float2(0.f, 0.f);
        rr = fmaf(pr, pr, fmaf(pi, pi, rr));
    }
    rr = blockReduceF(rr);
    if (threadIdx.x == 0) g_rr_part[blockIdx.x] = rr;
}

__global__ void k_sum_rr0() {
    float v = 0.f;
    for (int i = threadIdx.x; i < NB_EW; i += 256) v += g_rr_part[i];
    v = blockReduceF(v);
    if (threadIdx.x == 0) g_rr[0] = v;
}

// -------- K1: forward row FFTs with coil expand. 8 warps/CTA, 1 warp per row --------
__global__ __launch_bounds__(256) void k_rowfft_fwd(const float* __restrict__ cr,
                                                    const float* __restrict__ ci) {
    __shared__ float2 srow[8][224];
    __shared__ float2 sW[224];
    int tid = threadIdx.x;
    for (int i = tid; i < 224; i += 256) sW[i] = g_W224[i];
    __syncthreads();
    int warp = tid >> 5, t = tid & 31;
    float2 tw16 = sW[7  * (t & 15)];
    float2 tw8  = sW[14 * (t & 7)];
    float2 tw4  = sW[28 * (t & 3)];
    float2 tw2  = sW[56 * (t & 1)];
    int rid = blockIdx.x * 8 + warp;                 // < 53760
    int c = rid / (Dd * Hd);
    int r2 = rid - c * (Dd * Hd);
    int h = r2 % Hd;
    const float2* prow = g_p + r2 * Wd;
    const float* crr = cr + (c * Hd + h) * Wd;
    const float* cii = ci + (c * Hd + h) * Wd;
    float2 a[7];
    #pragma unroll
    for (int n1 = 0; n1 < 7; n1++) {
        int idx = n1 * 32 + t;
        float2 p = prow[idx];
        float2 co = make_float2(crr[idx], cii[idx]);
        a[n1] = cmulf(p, co);
    }
    float2 out[7];
    fft224_reg<false>(sW, t, tw16, tw8, tw4, tw2, a, out);
    int rt = bitrev5(t);
    #pragma unroll
    for (int k1 = 0; k1 < 7; k1++) srow[warp][7 * rt + k1] = out[k1];
    __syncwarp();
    float2* orow = g_scr + (size_t)rid * Wd;
    for (int j = t; j < 224; j += 32) orow[j] = srow[warp][j];
}

// -------- 448-pt column pass: symmetric radix-7 + local radix-4 + shuffle 4x4 16-DFT.
// Compute roles: s = tid&15 (within half-warp), g = tid>>4 (column).
// Thread (g,s) holds n2 = 16r+s; output out[k1][km] = X[7*(4*s+km)+k1] (natural order).
template<bool INV>
__device__ __forceinline__ void colpass(const float2* tile, const float2* sW,
                                        int g, int s, float2 out[7][4]) {
    float2 z[7][4];
    // stage 1: radix-7 over n1 + twiddle W448^{n2*k1}
    #pragma unroll
    for (int r = 0; r < 4; r++) {
        int n2 = 16 * r + s;
        float2 xin[7];
        #pragma unroll
        for (int n1 = 0; n1 < 7; n1++) xin[n1] = tile[(n1 * 64 + n2) * TSTR + g];
        float2 y[7];
        dft7<INV>(xin, y);
        #pragma unroll
        for (int k1 = 0; k1 < 7; k1++) {
            float2 tw = sW[n2 * k1];                 // <= 378 < 448
            if (INV) tw.y = -tw.y;
            z[k1][r] = cmulf(y[k1], tw);
        }
    }
    // stage 2: local radix-4 over r (trivial coeffs) + twiddle W64^{s*km}
    float2 w1 = sW[7  * s]; if (INV) w1.y = -w1.y;
    float2 w2 = sW[14 * s]; if (INV) w2.y = -w2.y;
    float2 w3 = sW[21 * s]; if (INV) w3.y = -w3.y;
    #pragma unroll
    for (int k1 = 0; k1 < 7; k1++) {
        float2 x0 = z[k1][0], x1 = z[k1][1], x2 = z[k1][2], x3 = z[k1][3];
        float2 t0 = cadd(x0, x2), t2 = csub(x0, x2);
        float2 t1 = cadd(x1, x3), t3 = csub(x1, x3);
        float2 it3 = INV ? make_float2(-t3.y, t3.x) : make_float2(t3.y, -t3.x);
        z[k1][0] = cadd(t0, t1);
        z[k1][1] = cmulf(cadd(t2, it3), w1);
        z[k1][2] = cmulf(csub(t0, t1), w2);
        z[k1][3] = cmulf(csub(t2, it3), w3);
    }
    // stage 3: 16-DFT across s = 4x4 DIT via half-warp shuffles.
    int jj = s & 3, kq = s >> 2;                 // stage A roles (this thread computes A[jj][kq])
    int m1 = kq & 3, m2 = (2 * kq) & 3, m3 = (3 * kq) & 3;
    float2 twA = sW[28 * jj * kq];               // W16^{jj*kq}; 28*9=252 < 448
    if (INV) twA.y = -twA.y;
    int kqB = s & 3, kj = s >> 2;                // stage B roles (this thread outputs k_s = s)
    int mb1 = kj & 3, mb2 = (2 * kj) & 3, mb3 = (3 * kj) & 3;
    #pragma unroll
    for (int k1 = 0; k1 < 7; k1++) {
        float2 A[4];
        #pragma unroll
        for (int km = 0; km < 4; km++) {
            float2 v = z[k1][km];
            float2 q0, q1, q2, q3;
            q0.x = __shfl_sync(0xffffffffu, v.x, jj,      16);
            q0.y = __shfl_sync(0xffffffffu, v.y, jj,      16);
            q1.x = __shfl_sync(0xffffffffu, v.x, jj + 4,  16);
            q1.y = __shfl_sync(0xffffffffu, v.y, jj + 4,  16);
            q2.x = __shfl_sync(0xffffffffu, v.x, jj + 8,  16);
            q2.y = __shfl_sync(0xffffffffu, v.y, jj + 8,  16);
            q3.x = __shfl_sync(0xffffffffu, v.x, jj + 12, 16);
            q3.y = __shfl_sync(0xffffffffu, v.y, jj + 12, 16);
            float2 acc = q0;
            acc = cadd(acc, w4rot<INV>(q1, m1));
            acc = cadd(acc, w4rot<INV>(q2, m2));
            acc = cadd(acc, w4rot<INV>(q3, m3));
            A[km] = cmulf(acc, twA);
        }
        #pragma unroll
        for (int km = 0; km < 4; km++) {
            float2 v = A[km];
            float2 h0, h1, h2, h3;
            int b0 = 4 * kqB;
            h0.x = __shfl_sync(0xffffffffu, v.x, b0,     16);
            h0.y = __shfl_sync(0xffffffffu, v.y, b0,     16);
            h1.x = __shfl_sync(0xffffffffu, v.x, b0 + 1, 16);
            h1.y = __shfl_sync(0xffffffffu, v.y, b0 + 1, 16);
            h2.x = __shfl_sync(0xffffffffu, v.x, b0 + 2, 16);
            h2.y = __shfl_sync(0xffffffffu, v.y, b0 + 2, 16);
            h3.x = __shfl_sync(0xffffffffu, v.x, b0 + 3, 16);
            h3.y = __shfl_sync(0xffffffffu, v.y, b0 + 3, 16);
            float2 acc = h0;
            acc = cadd(acc, w4rot<INV>(h1, mb1));
            acc = cadd(acc, w4rot<INV>(h2, mb2));
            acc = cadd(acc, w4rot<INV>(h3, mb3));
            out[k1][km] = acc;
        }
    }
}

// -------- K2: column FFT-448 + mask*(1/HW) + column IFFT-448, fused per 16-column tile
__global__ __launch_bounds__(256) void k_colfft(const int* __restrict__ mask) {
    extern __shared__ float2 sh[];                   // tile[448*TSTR] ++ W448[448]
    float2* tile = sh;
    float2* sW = sh + 448 * TSTR;
    int tid = threadIdx.x;
    for (int i = tid; i < 448; i += 256) sW[i] = g_W448[i];
    int wt = blockIdx.x % 14;
    int cd = blockIdx.x / 14;                        // c*D + d
    int w0 = wt * 16;
    float2* gbase = g_scr + (size_t)cd * HW;
    int lg = tid & 15, ls = tid >> 4;                // I/O roles (coalesced)
    int s = tid & 15, g = tid >> 4;                  // compute roles (s in half-warp)
    __syncthreads();
    for (int i = 0; i < 28; i++) {
        int h = ls + 16 * i;
        tile[h * TSTR + lg] = gbase[h * Wd + w0 + lg];
    }
    __syncthreads();
    float2 out[7][4];
    colpass<false>(tile, sW, g, s, out);
    __syncthreads();                                 // tile reads done before overwrite
    #pragma unroll
    for (int km = 0; km < 4; km++)
        #pragma unroll
        for (int k1 = 0; k1 < 7; k1++) {
            int k = 7 * (4 * s + km) + k1;
            float mv = mask[k * Wd + w0 + g] ? INV_HW : 0.f;
            tile[k * TSTR + g] = make_float2(out[k1][km].x * mv, out[k1][km].y * mv);
        }
    __syncthreads();
    colpass<true>(tile, sW, g, s, out);
    __syncthreads();                                 // tile reads done before overwrite
    #pragma unroll
    for (int km = 0; km < 4; km++)
        #pragma unroll
        for (int k1 = 0; k1 < 7; k1++) {
            int h = 7 * (4 * s + km) + k1;
            tile[h * TSTR + g] = out[k1][km];
        }
    __syncthreads();
    for (int i = 0; i < 28; i++) {
        int h = ls + 16 * i;
        gbase[h * Wd + w0 + lg] = tile[h * TSTR + lg];
    }
}

// -------- K3: inverse row FFTs + conj-coil combine + q = acc + mu*p; partial q.conj(p)
__global__ __launch_bounds__(256) void k_rowfft_inv(const float* __restrict__ cr,
                                                    const float* __restrict__ ci,
                                                    const float* __restrict__ miu) {
    __shared__ float2 srow[8][224];
    __shared__ float2 sprow[8][224];
    __shared__ float2 sW[224];
    int tid = threadIdx.x;
    for (int i = tid; i < 224; i += 256) sW[i] = g_W224[i];
    __syncthreads();
    int warp = tid >> 5, t = tid & 31;
    float2 tw16 = sW[7  * (t & 15)]; tw16.y = -tw16.y;
    float2 tw8  = sW[14 * (t & 7)];  tw8.y  = -tw8.y;
    float2 tw4  = sW[28 * (t & 3)];  tw4.y  = -tw4.y;
    float2 tw2  = sW[56 * (t & 1)];  tw2.y  = -tw2.y;
    int rid = blockIdx.x * 8 + warp;                 // < 5376 = D*H
    int h = rid % Hd;
    const float2* prow = g_p + (size_t)rid * Wd;
    for (int j = t; j < 224; j += 32) sprow[warp][j] = prow[j];
    __syncwarp();
    int rt = bitrev5(t);
    float2 accq[7];
    #pragma unroll
    for (int k1 = 0; k1 < 7; k1++) accq[k1] = make_float2(0.f, 0.f);
    for (int c = 0; c < Cd; c++) {
        const float2* srcrow = g_scr + ((size_t)c * DHW + (size_t)rid * Wd);
        float2 a[7];
        #pragma unroll
        for (int n1 = 0; n1 < 7; n1++) a[n1] = srcrow[n1 * 32 + t];
        float2 out[7];
        fft224_reg<true>(sW, t, tw16, tw8, tw4, tw2, a, out);
        const float* crr = cr + (c * Hd + h) * Wd;
        const float* cii = ci + (c * Hd + h) * Wd;
        #pragma unroll
        for (int k1 = 0; k1 < 7; k1++) {
            int x = 7 * rt + k1;
            float2 co = make_float2(crr[x], -cii[x]);   // conj(coil)
            cmadd(accq[k1], out[k1], co);
        }
    }
    float mu = fabsf(miu[0]);
    float2 qp = make_float2(0.f, 0.f);
    #pragma unroll
    for (int k1 = 0; k1 < 7; k1++) {
        int x = 7 * rt + k1;
        float2 p = sprow[warp][x];
        float2 q = make_float2(fmaf(mu, p.x, accq[k1].x), fmaf(mu, p.y, accq[k1].y));
        accq[k1] = q;
        qp.x += q.x * p.x + q.y * p.y;      // q * conj(p)
        qp.y += q.y * p.x - q.x * p.y;
    }
    __syncwarp();
    #pragma unroll
    for (int k1 = 0; k1 < 7; k1++) srow[warp][7 * rt + k1] = accq[k1];
    __syncwarp();
    float2* qrow = g_q + (size_t)rid * Wd;
    for (int j = t; j < 224; j += 32) qrow[j] = srow[warp][j];
    qp = blockReduceC(qp);
    if (tid == 0) g_qp_part[blockIdx.x] = qp;
}

// -------- alpha = rr / sum(q conj p) --------
__global__ void k_alpha(int it) {
    float2 v = make_float2(0.f, 0.f);
    for (int i = threadIdx.x; i < NB_Q; i += 256) {
        v.x += g_qp_part[i].x; v.y += g_qp_part[i].y;
    }
    v = blockReduceC(v);
    if (threadIdx.x == 0) {
        float rr = g_rr[it];
        float den = v.x * v.x + v.y * v.y;
        g_alpha[it] = make_float2(rr * v.x / den, -rr * v.y / den);
    }
}

// -------- b += alpha*p ; r -= alpha*q ; partial ||r||^2 --------
__global__ __launch_bounds__(256) void k_update_br(int it) {
    float2 al = g_alpha[it];
    float rr = 0.f;
    for (int n = blockIdx.x * 256 + threadIdx.x; n < DHW; n += NB_EW * 256) {
        float2 p = g_p[n], q = g_q[n], r = g_r[n], b = g_b[n];
        b.x += al.x * p.x - al.y * p.y;
        b.y += al.x * p.y + al.y * p.x;
        r.x -= al.x * q.x - al.y * q.y;
        r.y -= al.x * q.y + al.y * q.x;
        g_b[n] = b; g_r[n] = r;
        rr = fmaf(r.x, r.x, fmaf(r.y, r.y, rr));
    }
    rr = blockReduceF(rr);
    if (threadIdx.x == 0) g_rr_part[blockIdx.x] = rr;
}

__global__ void k_beta(int it) {
    float v = 0.f;
    for (int i = threadIdx.x; i < NB_EW; i += 256) v += g_rr_part[i];
    v = blockReduceF(v);
    if (threadIdx.x == 0) {
        g_rr[it + 1] = v;
        g_beta[it] = v / g_rr[it];
    }
}

// -------- p = r + beta*p --------
__global__ __launch_bounds__(256) void k_update_p(int it) {
    float be = g_beta[it];
    for (int n = blockIdx.x * 256 + threadIdx.x; n < DHW; n += NB_EW * 256) {
        float2 r = g_r[n], p = g_p[n];
        g_p[n] = make_float2(fmaf(be, p.x, r.x), fmaf(be, p.y, r.y));
    }
}

// -------- output: undo sign checkerboard --------
__global__ __launch_bounds__(256) void k_out(float* __restrict__ out) {
    for (int n = blockIdx.x * 256 + threadIdx.x; n < DHW; n += NB_EW * 256) {
        int w = n % Wd;
        int h = (n / Wd) % Hd;
        float s = ((h + w) & 1) ? -1.f : 1.f;
        float2 b = g_b[n];
        out[n] = s * b.x;
        out[DHW + n] = s * b.y;
    }
}

extern "C" void kernel_launch(void* const* d_in, const int* in_sizes, int n_in,
                              void* d_out, int out_size) {
    const float* z    = (const float*)d_in[0];
    const float* zf   = (const float*)d_in[1];
    const float* cr   = (const float*)d_in[2];
    const float* ci   = (const float*)d_in[3];
    const int*   mask = (const int*)d_in[4];
    const float* miu  = (const float*)d_in[5];
    float* out = (float*)d_out;

    const int k2_shmem = 448 * TSTR * (int)sizeof(float2) + 448 * (int)sizeof(float2); // 64512
    cudaFuncSetAttribute(k_colfft, cudaFuncAttributeMaxDynamicSharedMemorySize, k2_shmem);

    k_twiddle<<<1, 448>>>();
    k_init<<<NB_EW, 256>>>(z, zf, miu);
    k_sum_rr0<<<1, 256>>>();
    for (int it = 0; it < 5; ++it) {
        k_rowfft_fwd<<<6720, 256>>>(cr, ci);           // C*D*H/8
        k_colfft<<<1680, 256, k2_shmem>>>(mask);       // C*D*(W/16)
        k_rowfft_inv<<<NB_Q, 256>>>(cr, ci, miu);      // D*H/8
        k_alpha<<<1, 256>>>(it);
        k_update_br<<<NB_EW, 256>>>(it);
        k_beta<<<1, 256>>>(it);
        k_update_p<<<NB_EW, 256>>>(it);
    }
    k_out<<<NB_EW, 256>>>(out);
}

// round 4
// speedup vs baseline: 2.1571x; 1.0191x over previous
#include <cuda_runtime.h>
#include <math.h>

// Problem dims
#define Hd   448
#define Wd   224
#define Dd   12
#define Cd   10
#define HW   100352          // 448*224
#define DHW  1204224         // 12*HW
#define CDHW 12042240        // 10*DHW
#define INV_HW (1.0f/100352.0f)
#define NB_EW 1024           // blocks for elementwise+reduce kernels
#define NB_Q  672            // blocks for K3 (D*H/8)
#define PI_D 3.14159265358979323846
#define TSTR 17              // padded tile stride (float2) for K2

// -------- device scratch (static __device__ arrays: allocation-free) --------
__device__ float2 g_scr[CDHW];     // coil-expanded k-rows, w PERMUTED: j=32*k1+t <-> w=7*bitrev5(t)+k1
__device__ float2 g_p[DHW];
__device__ float2 g_r[DHW];
__device__ float2 g_b[DHW];
__device__ float2 g_q[DHW];
__device__ float2 g_W224[224];
__device__ float2 g_W448[448];
__device__ float  g_maskf[HW];     // permuted mask * INV_HW
__device__ float2 g_qp_part[NB_Q];
__device__ float  g_rrp[2][NB_EW]; // double-buffered ||r||^2 partials

// -------- complex helpers --------
__device__ __forceinline__ float2 cmulf(float2 a, float2 b) {
    return make_float2(a.x*b.x - a.y*b.y, a.x*b.y + a.y*b.x);
}
__device__ __forceinline__ void cmadd(float2& acc, float2 a, float2 b) {
    acc.x = fmaf(a.x, b.x, fmaf(-a.y, b.y, acc.x));
    acc.y = fmaf(a.x, b.y, fmaf( a.y, b.x, acc.y));
}
__device__ __forceinline__ float2 cadd(float2 a, float2 b){ return make_float2(a.x+b.x, a.y+b.y); }
__device__ __forceinline__ float2 csub(float2 a, float2 b){ return make_float2(a.x-b.x, a.y-b.y); }

__device__ __forceinline__ int bitrev5(int t) {
    return ((t & 1) << 4) | ((t & 2) << 2) | (t & 4) | ((t & 8) >> 2) | ((t & 16) >> 4);
}

// multiply by W4^m (forward W4 = -i); m in [0,4)
template<bool INV>
__device__ __forceinline__ float2 w4rot(float2 z, int m) {
    bool half = (m & 1) != 0;
    float rx = half ? (INV ? -z.y : z.y) : z.x;
    float ry = half ? (INV ?  z.x : -z.x) : z.y;
    if (m & 2) { rx = -rx; ry = -ry; }
    return make_float2(rx, ry);
}

// -------- symmetric DFT-7 (real-immediate coefficients) --------
template<bool INV>
__device__ __forceinline__ void dft7(const float2 x[7], float2 X[7]) {
    const float C1f =  0.62348980185873359f;   // cos(2pi/7)
    const float C2f = -0.22252093395631440f;   // cos(4pi/7)
    const float C3f = -0.90096886790241915f;   // cos(6pi/7)
    const float S1f =  0.78183148246802981f;   // sin(2pi/7)
    const float S2f =  0.97492791218182360f;   // sin(4pi/7)
    const float S3f =  0.43388373911755812f;   // sin(6pi/7)
    float2 a1 = cadd(x[1], x[6]), b1 = csub(x[1], x[6]);
    float2 a2 = cadd(x[2], x[5]), b2 = csub(x[2], x[5]);
    float2 a3 = cadd(x[3], x[4]), b3 = csub(x[3], x[4]);
    X[0] = make_float2(x[0].x + a1.x + a2.x + a3.x,
                       x[0].y + a1.y + a2.y + a3.y);
    float2 u1, u2, u3, v1, v2, v3;
    u1.x = fmaf(C1f,a1.x, fmaf(C2f,a2.x, fmaf(C3f,a3.x, x[0].x)));
    u1.y = fmaf(C1f,a1.y, fmaf(C2f,a2.y, fmaf(C3f,a3.y, x[0].y)));
    u2.x = fmaf(C2f,a1.x, fmaf(C3f,a2.x, fmaf(C1f,a3.x, x[0].x)));
    u2.y = fmaf(C2f,a1.y, fmaf(C3f,a2.y, fmaf(C1f,a3.y, x[0].y)));
    u3.x = fmaf(C3f,a1.x, fmaf(C1f,a2.x, fmaf(C2f,a3.x, x[0].x)));
    u3.y = fmaf(C3f,a1.y, fmaf(C1f,a2.y, fmaf(C2f,a3.y, x[0].y)));
    v1.x = fmaf(S1f,b1.x, fmaf( S2f,b2.x,  S3f*b3.x));
    v1.y = fmaf(S1f,b1.y, fmaf( S2f,b2.y,  S3f*b3.y));
    v2.x = fmaf(S2f,b1.x, fmaf(-S3f,b2.x, -S1f*b3.x));
    v2.y = fmaf(S2f,b1.y, fmaf(-S3f,b2.y, -S1f*b3.y));
    v3.x = fmaf(S3f,b1.x, fmaf(-S1f,b2.x,  S2f*b3.x));
    v3.y = fmaf(S3f,b1.y, fmaf(-S1f,b2.y,  S2f*b3.y));
    if (!INV) {
        X[1] = make_float2(u1.x + v1.y, u1.y - v1.x);
        X[6] = make_float2(u1.x - v1.y, u1.y + v1.x);
        X[2] = make_float2(u2.x + v2.y, u2.y - v2.x);
        X[5] = make_float2(u2.x - v2.y, u2.y + v2.x);
        X[3] = make_float2(u3.x + v3.y, u3.y - v3.x);
        X[4] = make_float2(u3.x - v3.y, u3.y + v3.x);
    } else {
        X[1] = make_float2(u1.x - v1.y, u1.y + v1.x);
        X[6] = make_float2(u1.x + v1.y, u1.y - v1.x);
        X[2] = make_float2(u2.x - v2.y, u2.y + v2.x);
        X[5] = make_float2(u2.x + v2.y, u2.y - v2.x);
        X[3] = make_float2(u3.x - v3.y, u3.y + v3.x);
        X[4] = make_float2(u3.x + v3.y, u3.y - v3.x);
    }
}

// forward radix-2 DIF butterfly across lanes
__device__ __forceinline__ void bfly(float2& v, int t, int m, float2 tw) {
    float2 o;
    o.x = __shfl_xor_sync(0xffffffffu, v.x, m);
    o.y = __shfl_xor_sync(0xffffffffu, v.y, m);
    float2 sum = make_float2(v.x + o.x, v.y + o.y);
    float2 dif = make_float2(o.x - v.x, o.y - v.y);
    float2 dm  = cmulf(dif, tw);
    v = (t & m) ? dm : sum;
}

// inverse radix-2 DIT butterfly (twc = conj of the forward stage twiddle):
// high lane pre-multiplies by twc, then exchange, then a=y0+y1*twc, b=y0-y1*twc
__device__ __forceinline__ void ibfly(float2& v, int t, int m, float2 twc) {
    float2 vv = v;
    if (t & m) vv = cmulf(v, twc);
    float2 o;
    o.x = __shfl_xor_sync(0xffffffffu, vv.x, m);
    o.y = __shfl_xor_sync(0xffffffffu, vv.y, m);
    v = (t & m) ? csub(o, vv) : cadd(vv, o);
}

// -------- deterministic block reductions (trailing sync: safe to call repeatedly) --------
__device__ __forceinline__ float blockReduceF(float v) {
    __shared__ float red[8];
    int lane = threadIdx.x & 31, wp = threadIdx.x >> 5;
    #pragma unroll
    for (int o = 16; o > 0; o >>= 1) v += __shfl_down_sync(0xffffffffu, v, o);
    if (lane == 0) red[wp] = v;
    __syncthreads();
    if (wp == 0) {
        v = (lane < 8) ? red[lane] : 0.f;
        #pragma unroll
        for (int o = 4; o > 0; o >>= 1) v += __shfl_down_sync(0xffffffffu, v, o);
    }
    __syncthreads();
    return v;   // valid on thread 0
}
__device__ __forceinline__ float2 blockReduceC(float2 v) {
    __shared__ float2 redc[8];
    int lane = threadIdx.x & 31, wp = threadIdx.x >> 5;
    #pragma unroll
    for (int o = 16; o > 0; o >>= 1) {
        v.x += __shfl_down_sync(0xffffffffu, v.x, o);
        v.y += __shfl_down_sync(0xffffffffu, v.y, o);
    }
    if (lane == 0) redc[wp] = v;
    __syncthreads();
    if (wp == 0) {
        v = (lane < 8) ? redc[lane] : make_float2(0.f, 0.f);
        #pragma unroll
        for (int o = 4; o > 0; o >>= 1) {
            v.x += __shfl_down_sync(0xffffffffu, v.x, o);
            v.y += __shfl_down_sync(0xffffffffu, v.y, o);
        }
    }
    __syncthreads();
    return v;
}

// -------- twiddle init --------
__global__ void k_twiddle() {
    int i = threadIdx.x;
    if (i < 224) {
        double a = -2.0 * PI_D * (double)i / 224.0;
        g_W224[i] = make_float2((float)cos(a), (float)sin(a));
    }
    if (i < 448) {
        double a = -2.0 * PI_D * (double)i / 448.0;
        g_W448[i] = make_float2((float)cos(a), (float)sin(a));
    }
}

// -------- permuted mask table: maskf[k*Wd + j] = mask[k*Wd + wtrue(j)] * INV_HW --------
__global__ void k_maskf(const int* __restrict__ mask) {
    int idx = blockIdx.x * 256 + threadIdx.x;
    if (idx < HW) {
        int j = idx % Wd;
        int k = idx / Wd;
        int t = j & 31, k1 = j >> 5;
        int wt = 7 * bitrev5(t) + k1;
        g_maskf[idx] = mask[k * Wd + wt] ? INV_HW : 0.f;
    }
}

// -------- forward 224-pt FFT per warp: symmetric radix-7 + shuffle DIF FFT-32.
// Input: a[n1] = x[32*n1 + t].  Output: out[k1] = X[7*bitrev5(t) + k1].
__device__ __forceinline__ void fft224_fwd(const float2* sW, int t,
        float2 tw16, float2 tw8, float2 tw4, float2 tw2,
        const float2 a[7], float2 out[7]) {
    float2 y[7];
    dft7<false>(a, y);
    #pragma unroll
    for (int k1 = 0; k1 < 7; k1++) {
        float2 twt = sW[t * k1];          // t*k1 <= 186 < 224
        float2 v = cmulf(y[k1], twt);
        bfly(v, t, 16, tw16);
        bfly(v, t,  8, tw8);
        bfly(v, t,  4, tw4);
        bfly(v, t,  2, tw2);
        float2 o;
        o.x = __shfl_xor_sync(0xffffffffu, v.x, 1);
        o.y = __shfl_xor_sync(0xffffffffu, v.y, 1);
        v = (t & 1) ? make_float2(o.x - v.x, o.y - v.y)
                    : make_float2(v.x + o.x, v.y + o.y);
        out[k1] = v;
    }
}

// -------- inverse 224-pt FFT per warp, consuming permuted (DIF) order natively.
// Input: y[k1] = stored[32*k1+t] = X[7*bitrev5(t)+k1]. Output: xo[n1] = x[32*n1+t].
__device__ __forceinline__ void fft224_inv(const float2* sW, int t,
        float2 tw16c, float2 tw8c, float2 tw4c, float2 tw2c,
        float2 y[7], float2 xo[7]) {
    #pragma unroll
    for (int k1 = 0; k1 < 7; k1++) {
        float2 v = y[k1];
        float2 o;                                      // stage m=1: plain
        o.x = __shfl_xor_sync(0xffffffffu, v.x, 1);
        o.y = __shfl_xor_sync(0xffffffffu, v.y, 1);
        v = (t & 1) ? csub(o, v) : cadd(v, o);
        ibfly(v, t,  2, tw2c);
        ibfly(v, t,  4, tw4c);
        ibfly(v, t,  8, tw8c);
        ibfly(v, t, 16, tw16c);
        float2 tw = sW[t * k1]; tw.y = -tw.y;          // conj twiddle
        y[k1] = cmulf(v, tw);
    }
    dft7<true>(y, xo);
}

// -------- K0: p = s*(zf + mu*z); r = p; b = 0; partial ||p||^2 --------
__global__ __launch_bounds__(256) void k_init(const float* __restrict__ z,
                                              const float* __restrict__ zf,
                                              const float* __restrict__ miu) {
    float mu = fabsf(miu[0]);
    float rr = 0.f;
    for (int n = blockIdx.x * 256 + threadIdx.x; n < DHW; n += NB_EW * 256) {
        int w = n % Wd;
        int h = (n / Wd) % Hd;
        float s = ((h + w) & 1) ? -1.f : 1.f;
        float pr = s * (zf[n] + mu * z[n]);
        float pi = s * (zf[DHW + n] + mu * z[DHW + n]);
        float2 p = make_float2(pr, pi);
        g_p[n] = p; g_r[n] = p; g_b[n] = make_float2(0.f, 0.f);
        rr = fmaf(pr, pr, fmaf(pi, pi, rr));
    }
    rr = blockReduceF(rr);
    if (threadIdx.x == 0) g_rrp[0][blockIdx.x] = rr;
}

// -------- K1: forward row FFTs with coil expand; direct permuted coalesced store --------
__global__ __launch_bounds__(256) void k_rowfft_fwd(const float* __restrict__ cr,
                                                    const float* __restrict__ ci) {
    __shared__ float2 sW[224];
    int tid = threadIdx.x;
    for (int i = tid; i < 224; i += 256) sW[i] = g_W224[i];
    __syncthreads();
    int warp = tid >> 5, t = tid & 31;
    float2 tw16 = sW[7  * (t & 15)];
    float2 tw8  = sW[14 * (t & 7)];
    float2 tw4  = sW[28 * (t & 3)];
    float2 tw2  = sW[56 * (t & 1)];
    int rid = blockIdx.x * 8 + warp;                 // < 53760
    int c = rid / (Dd * Hd);
    int r2 = rid - c * (Dd * Hd);
    int h = r2 % Hd;
    const float2* prow = g_p + r2 * Wd;
    const float* crr = cr + (c * Hd + h) * Wd;
    const float* cii = ci + (c * Hd + h) * Wd;
    float2 a[7];
    #pragma unroll
    for (int n1 = 0; n1 < 7; n1++) {
        int idx = n1 * 32 + t;
        float2 p = prow[idx];
        float2 co = make_float2(crr[idx], cii[idx]);
        a[n1] = cmulf(p, co);
    }
    float2 out[7];
    fft224_fwd(sW, t, tw16, tw8, tw4, tw2, a, out);
    float2* orow = g_scr + (size_t)rid * Wd;
    #pragma unroll
    for (int k1 = 0; k1 < 7; k1++) orow[k1 * 32 + t] = out[k1];   // permuted, coalesced
}

// -------- 448-pt column pass: symmetric radix-7 + local radix-4 + shuffle 4x4 16-DFT.
template<bool INV>
__device__ __forceinline__ void colpass(const float2* tile, const float2* sW,
                                        int g, int s, float2 out[7][4]) {
    float2 z[7][4];
    #pragma unroll
    for (int r = 0; r < 4; r++) {
        int n2 = 16 * r + s;
        float2 xin[7];
        #pragma unroll
        for (int n1 = 0; n1 < 7; n1++) xin[n1] = tile[(n1 * 64 + n2) * TSTR + g];
        float2 y[7];
        dft7<INV>(xin, y);
        #pragma unroll
        for (int k1 = 0; k1 < 7; k1++) {
            float2 tw = sW[n2 * k1];                 // <= 378 < 448
            if (INV) tw.y = -tw.y;
            z[k1][r] = cmulf(y[k1], tw);
        }
    }
    float2 w1 = sW[7  * s]; if (INV) w1.y = -w1.y;
    float2 w2 = sW[14 * s]; if (INV) w2.y = -w2.y;
    float2 w3 = sW[21 * s]; if (INV) w3.y = -w3.y;
    #pragma unroll
    for (int k1 = 0; k1 < 7; k1++) {
        float2 x0 = z[k1][0], x1 = z[k1][1], x2 = z[k1][2], x3 = z[k1][3];
        float2 t0 = cadd(x0, x2), t2 = csub(x0, x2);
        float2 t1 = cadd(x1, x3), t3 = csub(x1, x3);
        float2 it3 = INV ? make_float2(-t3.y, t3.x) : make_float2(t3.y, -t3.x);
        z[k1][0] = cadd(t0, t1);
        z[k1][1] = cmulf(cadd(t2, it3), w1);
        z[k1][2] = cmulf(csub(t0, t1), w2);
        z[k1][3] = cmulf(csub(t2, it3), w3);
    }
    int jj = s & 3, kq = s >> 2;
    int m1 = kq & 3, m2 = (2 * kq) & 3, m3 = (3 * kq) & 3;
    float2 twA = sW[28 * jj * kq];
    if (INV) twA.y = -twA.y;
    int kqB = s & 3, kj = s >> 2;
    int mb1 = kj & 3, mb2 = (2 * kj) & 3, mb3 = (3 * kj) & 3;
    #pragma unroll
    for (int k1 = 0; k1 < 7; k1++) {
        float2 A[4];
        #pragma unroll
        for (int km = 0; km < 4; km++) {
            float2 v = z[k1][km];
            float2 q0, q1, q2, q3;
            q0.x = __shfl_sync(0xffffffffu, v.x, jj,      16);
            q0.y = __shfl_sync(0xffffffffu, v.y, jj,      16);
            q1.x = __shfl_sync(0xffffffffu, v.x, jj + 4,  16);
            q1.y = __shfl_sync(0xffffffffu, v.y, jj + 4,  16);
            q2.x = __shfl_sync(0xffffffffu, v.x, jj + 8,  16);
            q2.y = __shfl_sync(0xffffffffu, v.y, jj + 8,  16);
            q3.x = __shfl_sync(0xffffffffu, v.x, jj + 12, 16);
            q3.y = __shfl_sync(0xffffffffu, v.y, jj + 12, 16);
            float2 acc = q0;
            acc = cadd(acc, w4rot<INV>(q1, m1));
            acc = cadd(acc, w4rot<INV>(q2, m2));
            acc = cadd(acc, w4rot<INV>(q3, m3));
            A[km] = cmulf(acc, twA);
        }
        #pragma unroll
        for (int km = 0; km < 4; km++) {
            float2 v = A[km];
            float2 h0, h1, h2, h3;
            int b0 = 4 * kqB;
            h0.x = __shfl_sync(0xffffffffu, v.x, b0,     16);
            h0.y = __shfl_sync(0xffffffffu, v.y, b0,     16);
            h1.x = __shfl_sync(0xffffffffu, v.x, b0 + 1, 16);
            h1.y = __shfl_sync(0xffffffffu, v.y, b0 + 1, 16);
            h2.x = __shfl_sync(0xffffffffu, v.x, b0 + 2, 16);
            h2.y = __shfl_sync(0xffffffffu, v.y, b0 + 2, 16);
            h3.x = __shfl_sync(0xffffffffu, v.x, b0 + 3, 16);
            h3.y = __shfl_sync(0xffffffffu, v.y, b0 + 3, 16);
            float2 acc = h0;
            acc = cadd(acc, w4rot<INV>(h1, mb1));
            acc = cadd(acc, w4rot<INV>(h2, mb2));
            acc = cadd(acc, w4rot<INV>(h3, mb3));
            out[k1][km] = acc;
        }
    }
}

// -------- K2: column FFT-448 + maskf + column IFFT-448, fused per 16-column tile --------
__global__ __launch_bounds__(256) void k_colfft() {
    extern __shared__ float2 sh[];                   // tile[448*TSTR] ++ W448[448]
    float2* tile = sh;
    float2* sW = sh + 448 * TSTR;
    int tid = threadIdx.x;
    for (int i = tid; i < 448; i += 256) sW[i] = g_W448[i];
    int wt = blockIdx.x % 14;
    int cd = blockIdx.x / 14;                        // c*D + d
    int w0 = wt * 16;
    float2* gbase = g_scr + (size_t)cd * HW;
    int lg = tid & 15, ls = tid >> 4;                // I/O roles (coalesced)
    int s = tid & 15, g = tid >> 4;                  // compute roles (s in half-warp)
    __syncthreads();
    for (int i = 0; i < 28; i++) {
        int h = ls + 16 * i;
        tile[h * TSTR + lg] = gbase[h * Wd + w0 + lg];
    }
    __syncthreads();
    float2 out[7][4];
    colpass<false>(tile, sW, g, s, out);
    __syncthreads();
    #pragma unroll
    for (int km = 0; km < 4; km++)
        #pragma unroll
        for (int k1 = 0; k1 < 7; k1++) {
            int k = 7 * (4 * s + km) + k1;
            float mv = g_maskf[k * Wd + w0 + g];
            tile[k * TSTR + g] = make_float2(out[k1][km].x * mv, out[k1][km].y * mv);
        }
    __syncthreads();
    colpass<true>(tile, sW, g, s, out);
    __syncthreads();
    #pragma unroll
    for (int km = 0; km < 4; km++)
        #pragma unroll
        for (int k1 = 0; k1 < 7; k1++) {
            int h = 7 * (4 * s + km) + k1;
            tile[h * TSTR + g] = out[k1][km];
        }
    __syncthreads();
    for (int i = 0; i < 28; i++) {
        int h = ls + 16 * i;
        gbase[h * Wd + w0 + lg] = tile[h * TSTR + lg];
    }
}

// -------- K3: DIT inverse row FFTs (permuted input) + conj-coil combine + q; partial q.conj(p)
__global__ __launch_bounds__(256) void k_rowfft_inv(const float* __restrict__ cr,
                                                    const float* __restrict__ ci,
                                                    const float* __restrict__ miu) {
    __shared__ float2 sW[224];
    int tid = threadIdx.x;
    for (int i = tid; i < 224; i += 256) sW[i] = g_W224[i];
    __syncthreads();
    int warp = tid >> 5, t = tid & 31;
    float2 tw16c = sW[7  * (t & 15)]; tw16c.y = -tw16c.y;
    float2 tw8c  = sW[14 * (t & 7)];  tw8c.y  = -tw8c.y;
    float2 tw4c  = sW[28 * (t & 3)];  tw4c.y  = -tw4c.y;
    float2 tw2c  = sW[56 * (t & 1)];  tw2c.y  = -tw2c.y;
    int rid = blockIdx.x * 8 + warp;                 // < 5376 = D*H
    int h = rid % Hd;
    float2 accq[7];
    #pragma unroll
    for (int n1 = 0; n1 < 7; n1++) accq[n1] = make_float2(0.f, 0.f);
    for (int c = 0; c < Cd; c++) {
        const float2* srcrow = g_scr + ((size_t)c * DHW + (size_t)rid * Wd);
        float2 y[7];
        #pragma unroll
        for (int k1 = 0; k1 < 7; k1++) y[k1] = srcrow[k1 * 32 + t];   // coalesced
        float2 xo[7];
        fft224_inv(sW, t, tw16c, tw8c, tw4c, tw2c, y, xo);
        const float* crr = cr + (c * Hd + h) * Wd;
        const float* cii = ci + (c * Hd + h) * Wd;
        #pragma unroll
        for (int n1 = 0; n1 < 7; n1++) {
            int x = n1 * 32 + t;
            float2 co = make_float2(crr[x], -cii[x]);   // conj(coil)
            cmadd(accq[n1], xo[n1], co);
        }
    }
    float mu = fabsf(miu[0]);
    float2 qp = make_float2(0.f, 0.f);
    const float2* prow = g_p + (size_t)rid * Wd;
    float2* qrow = g_q + (size_t)rid * Wd;
    #pragma unroll
    for (int n1 = 0; n1 < 7; n1++) {
        int x = n1 * 32 + t;
        float2 p = prow[x];
        float2 q = make_float2(fmaf(mu, p.x, accq[n1].x), fmaf(mu, p.y, accq[n1].y));
        qrow[x] = q;
        qp.x += q.x * p.x + q.y * p.y;      // q * conj(p)
        qp.y += q.y * p.x - q.x * p.y;
    }
    qp = blockReduceC(qp);
    if (tid == 0) g_qp_part[blockIdx.x] = qp;
}

// -------- fused: alpha = rr/sum(q conj p); b += alpha*p; r -= alpha*q; new ||r||^2 partials
__global__ __launch_bounds__(256) void k_update_br(int it) {
    __shared__ float2 s_al;
    int tid = threadIdx.x;
    float2 qp = make_float2(0.f, 0.f);
    for (int i = tid; i < NB_Q; i += 256) { qp.x += g_qp_part[i].x; qp.y += g_qp_part[i].y; }
    qp = blockReduceC(qp);
    float rrv = 0.f;
    for (int i = tid; i < NB_EW; i += 256) rrv += g_rrp[it & 1][i];
    rrv = blockReduceF(rrv);
    if (tid == 0) {
        float den = qp.x * qp.x + qp.y * qp.y;
        s_al = make_float2(rrv * qp.x / den, -rrv * qp.y / den);
    }
    __syncthreads();
    float2 al = s_al;
    float rr = 0.f;
    for (int n = blockIdx.x * 256 + tid; n < DHW; n += NB_EW * 256) {
        float2 p = g_p[n], q = g_q[n], r = g_r[n], b = g_b[n];
        b.x += al.x * p.x - al.y * p.y;
        b.y += al.x * p.y + al.y * p.x;
        r.x -= al.x * q.x - al.y * q.y;
        r.y -= al.x * q.y + al.y * q.x;
        g_b[n] = b; g_r[n] = r;
        rr = fmaf(r.x, r.x, fmaf(r.y, r.y, rr));
    }
    rr = blockReduceF(rr);
    if (tid == 0) g_rrp[(it + 1) & 1][blockIdx.x] = rr;
}

// -------- fused: beta = rr_new/rr_old; p = r + beta*p --------
__global__ __launch_bounds__(256) void k_update_p(int it) {
    __shared__ float s_be;
    int tid = threadIdx.x;
    float2 v = make_float2(0.f, 0.f);
    for (int i = tid; i < NB_EW; i += 256) {
        v.x += g_rrp[(it + 1) & 1][i];
        v.y += g_rrp[it & 1][i];
    }
    v = blockReduceC(v);
    if (tid == 0) s_be = v.x / v.y;
    __syncthreads();
    float be = s_be;
    for (int n = blockIdx.x * 256 + tid; n < DHW; n += NB_EW * 256) {
        float2 r = g_r[n], p = g_p[n];
        g_p[n] = make_float2(fmaf(be, p.x, r.x), fmaf(be, p.y, r.y));
    }
}

// -------- output: undo sign checkerboard --------
__global__ __launch_bounds__(256) void k_out(float* __restrict__ out) {
    for (int n = blockIdx.x * 256 + threadIdx.x; n < DHW; n += NB_EW * 256) {
        int w = n % Wd;
        int h = (n / Wd) % Hd;
        float s = ((h + w) & 1) ? -1.f : 1.f;
        float2 b = g_b[n];
        out[n] = s * b.x;
        out[DHW + n] = s * b.y;
    }
}

extern "C" void kernel_launch(void* const* d_in, const int* in_sizes, int n_in,
                              void* d_out, int out_size) {
    const float* z    = (const float*)d_in[0];
    const float* zf   = (const float*)d_in[1];
    const float* cr   = (const float*)d_in[2];
    const float* ci   = (const float*)d_in[3];
    const int*   mask = (const int*)d_in[4];
    const float* miu  = (const float*)d_in[5];
    float* out = (float*)d_out;

    const int k2_shmem = 448 * TSTR * (int)sizeof(float2) + 448 * (int)sizeof(float2); // 64512
    cudaFuncSetAttribute(k_colfft, cudaFuncAttributeMaxDynamicSharedMemorySize, k2_shmem);

    k_twiddle<<<1, 448>>>();
    k_maskf<<<(HW + 255) / 256, 256>>>(mask);
    k_init<<<NB_EW, 256>>>(z, zf, miu);
    for (int it = 0; it < 5; ++it) {
        k_rowfft_fwd<<<6720, 256>>>(cr, ci);           // C*D*H/8
        k_colfft<<<1680, 256, k2_shmem>>>();           // C*D*(W/16)
        k_rowfft_inv<<<NB_Q, 256>>>(cr, ci, miu);      // D*H/8
        k_update_br<<<NB_EW, 256>>>(it);
        if (it < 4) k_update_p<<<NB_EW, 256>>>(it);
    }
    k_out<<<NB_EW, 256>>>(out);
}

// round 5
// speedup vs baseline: 2.5325x; 1.1740x over previous
#include <cuda_runtime.h>
#include <math.h>

// Problem dims
#define Hd   448
#define Wd   224
#define Dd   12
#define Cd   10
#define HW   100352          // 448*224
#define DHW  1204224         // 12*HW
#define CDHW 12042240        // 10*DHW
#define INV_HW (1.0f/100352.0f)
#define NB_EW 1024           // blocks for elementwise+reduce kernels
#define NB_Q  672            // blocks for K3 (D*H/8)
#define PI_D 3.14159265358979323846
#define TSTR 17              // padded tile stride (float2) for K2

// -------- device scratch (static __device__ arrays: allocation-free) --------
__device__ float2 g_scr[CDHW];     // coil-expanded k-rows, w PERMUTED: j=32*k1+t <-> w=7*bitrev5(t)+k1
__device__ float2 g_p[DHW];
__device__ float2 g_r[DHW];
__device__ float2 g_b[DHW];
__device__ float2 g_q[DHW];
__device__ float2 g_W224[224];
__device__ float2 g_W448[448];
__device__ float  g_maskf[HW];     // fully permuted (k and w) mask * INV_HW
__device__ float2 g_qp_part[NB_Q];
__device__ float  g_rrp[2][NB_EW]; // double-buffered ||r||^2 partials

// -------- complex helpers --------
__device__ __forceinline__ float2 cmulf(float2 a, float2 b) {
    return make_float2(a.x*b.x - a.y*b.y, a.x*b.y + a.y*b.x);
}
__device__ __forceinline__ void cmadd(float2& acc, float2 a, float2 b) {
    acc.x = fmaf(a.x, b.x, fmaf(-a.y, b.y, acc.x));
    acc.y = fmaf(a.x, b.y, fmaf( a.y, b.x, acc.y));
}
__device__ __forceinline__ float2 cadd(float2 a, float2 b){ return make_float2(a.x+b.x, a.y+b.y); }
__device__ __forceinline__ float2 csub(float2 a, float2 b){ return make_float2(a.x-b.x, a.y-b.y); }

__device__ __forceinline__ int bitrev5(int t) {
    return ((t & 1) << 4) | ((t & 2) << 2) | (t & 4) | ((t & 8) >> 2) | ((t & 16) >> 4);
}
__device__ __forceinline__ int bitrev4(int s) {
    return ((s & 1) << 3) | ((s & 2) << 1) | ((s & 4) >> 1) | ((s & 8) >> 3);
}

// -------- symmetric DFT-7 (real-immediate coefficients) --------
template<bool INV>
__device__ __forceinline__ void dft7(const float2 x[7], float2 X[7]) {
    const float C1f =  0.62348980185873359f;   // cos(2pi/7)
    const float C2f = -0.22252093395631440f;   // cos(4pi/7)
    const float C3f = -0.90096886790241915f;   // cos(6pi/7)
    const float S1f =  0.78183148246802981f;   // sin(2pi/7)
    const float S2f =  0.97492791218182360f;   // sin(4pi/7)
    const float S3f =  0.43388373911755812f;   // sin(6pi/7)
    float2 a1 = cadd(x[1], x[6]), b1 = csub(x[1], x[6]);
    float2 a2 = cadd(x[2], x[5]), b2 = csub(x[2], x[5]);
    float2 a3 = cadd(x[3], x[4]), b3 = csub(x[3], x[4]);
    X[0] = make_float2(x[0].x + a1.x + a2.x + a3.x,
                       x[0].y + a1.y + a2.y + a3.y);
    float2 u1, u2, u3, v1, v2, v3;
    u1.x = fmaf(C1f,a1.x, fmaf(C2f,a2.x, fmaf(C3f,a3.x, x[0].x)));
    u1.y = fmaf(C1f,a1.y, fmaf(C2f,a2.y, fmaf(C3f,a3.y, x[0].y)));
    u2.x = fmaf(C2f,a1.x, fmaf(C3f,a2.x, fmaf(C1f,a3.x, x[0].x)));
    u2.y = fmaf(C2f,a1.y, fmaf(C3f,a2.y, fmaf(C1f,a3.y, x[0].y)));
    u3.x = fmaf(C3f,a1.x, fmaf(C1f,a2.x, fmaf(C2f,a3.x, x[0].x)));
    u3.y = fmaf(C3f,a1.y, fmaf(C1f,a2.y, fmaf(C2f,a3.y, x[0].y)));
    v1.x = fmaf(S1f,b1.x, fmaf( S2f,b2.x,  S3f*b3.x));
    v1.y = fmaf(S1f,b1.y, fmaf( S2f,b2.y,  S3f*b3.y));
    v2.x = fmaf(S2f,b1.x, fmaf(-S3f,b2.x, -S1f*b3.x));
    v2.y = fmaf(S2f,b1.y, fmaf(-S3f,b2.y, -S1f*b3.y));
    v3.x = fmaf(S3f,b1.x, fmaf(-S1f,b2.x,  S2f*b3.x));
    v3.y = fmaf(S3f,b1.y, fmaf(-S1f,b2.y,  S2f*b3.y));
    if (!INV) {
        X[1] = make_float2(u1.x + v1.y, u1.y - v1.x);
        X[6] = make_float2(u1.x - v1.y, u1.y + v1.x);
        X[2] = make_float2(u2.x + v2.y, u2.y - v2.x);
        X[5] = make_float2(u2.x - v2.y, u2.y + v2.x);
        X[3] = make_float2(u3.x + v3.y, u3.y - v3.x);
        X[4] = make_float2(u3.x - v3.y, u3.y + v3.x);
    } else {
        X[1] = make_float2(u1.x - v1.y, u1.y + v1.x);
        X[6] = make_float2(u1.x + v1.y, u1.y - v1.x);
        X[2] = make_float2(u2.x - v2.y, u2.y + v2.x);
        X[5] = make_float2(u2.x + v2.y, u2.y - v2.x);
        X[3] = make_float2(u3.x - v3.y, u3.y + v3.x);
        X[4] = make_float2(u3.x + v3.y, u3.y - v3.x);
    }
}

// forward radix-2 DIF butterfly across lanes
__device__ __forceinline__ void bfly(float2& v, int t, int m, float2 tw) {
    float2 o;
    o.x = __shfl_xor_sync(0xffffffffu, v.x, m);
    o.y = __shfl_xor_sync(0xffffffffu, v.y, m);
    float2 sum = make_float2(v.x + o.x, v.y + o.y);
    float2 dif = make_float2(o.x - v.x, o.y - v.y);
    float2 dm  = cmulf(dif, tw);
    v = (t & m) ? dm : sum;
}

// inverse radix-2 DIT butterfly (twc = conj of the forward stage twiddle)
__device__ __forceinline__ void ibfly(float2& v, int t, int m, float2 twc) {
    float2 vv = v;
    if (t & m) vv = cmulf(v, twc);
    float2 o;
    o.x = __shfl_xor_sync(0xffffffffu, vv.x, m);
    o.y = __shfl_xor_sync(0xffffffffu, vv.y, m);
    v = (t & m) ? csub(o, vv) : cadd(vv, o);
}

// -------- deterministic block reductions (trailing sync: safe to call repeatedly) --------
__device__ __forceinline__ float blockReduceF(float v) {
    __shared__ float red[8];
    int lane = threadIdx.x & 31, wp = threadIdx.x >> 5;
    #pragma unroll
    for (int o = 16; o > 0; o >>= 1) v += __shfl_down_sync(0xffffffffu, v, o);
    if (lane == 0) red[wp] = v;
    __syncthreads();
    if (wp == 0) {
        v = (lane < 8) ? red[lane] : 0.f;
        #pragma unroll
        for (int o = 4; o > 0; o >>= 1) v += __shfl_down_sync(0xffffffffu, v, o);
    }
    __syncthreads();
    return v;   // valid on thread 0
}
__device__ __forceinline__ float2 blockReduceC(float2 v) {
    __shared__ float2 redc[8];
    int lane = threadIdx.x & 31, wp = threadIdx.x >> 5;
    #pragma unroll
    for (int o = 16; o > 0; o >>= 1) {
        v.x += __shfl_down_sync(0xffffffffu, v.x, o);
        v.y += __shfl_down_sync(0xffffffffu, v.y, o);
    }
    if (lane == 0) redc[wp] = v;
    __syncthreads();
    if (wp == 0) {
        v = (lane < 8) ? redc[lane] : make_float2(0.f, 0.f);
        #pragma unroll
        for (int o = 4; o > 0; o >>= 1) {
            v.x += __shfl_down_sync(0xffffffffu, v.x, o);
            v.y += __shfl_down_sync(0xffffffffu, v.y, o);
        }
    }
    __syncthreads();
    return v;
}

// -------- twiddle init --------
__global__ void k_twiddle() {
    int i = threadIdx.x;
    if (i < 224) {
        double a = -2.0 * PI_D * (double)i / 224.0;
        g_W224[i] = make_float2((float)cos(a), (float)sin(a));
    }
    if (i < 448) {
        double a = -2.0 * PI_D * (double)i / 448.0;
        g_W448[i] = make_float2((float)cos(a), (float)sin(a));
    }
}

// -------- fully permuted mask table --------
// storage slot kidx = 7*(4*s+km)+k1  <->  true k = 7*(4*bitrev4(s)+km)+k1
// storage col  j    = 32*k1w + t     <->  true w = 7*bitrev5(t)+k1w
__global__ void k_maskf(const int* __restrict__ mask) {
    int idx = blockIdx.x * 256 + threadIdx.x;
    if (idx < HW) {
        int j = idx % Wd;
        int kidx = idx / Wd;
        int t = j & 31, k1w = j >> 5;
        int wt = 7 * bitrev5(t) + k1w;
        int k1 = kidx % 7, q = kidx / 7;
        int s = q >> 2, km = q & 3;
        int ktrue = 7 * (4 * bitrev4(s) + km) + k1;
        g_maskf[idx] = mask[ktrue * Wd + wt] ? INV_HW : 0.f;
    }
}

// -------- forward 224-pt FFT per warp: symmetric radix-7 + shuffle DIF FFT-32.
// Input: a[n1] = x[32*n1 + t].  Output: out[k1] = X[7*bitrev5(t) + k1].
__device__ __forceinline__ void fft224_fwd(const float2* sW, int t,
        float2 tw16, float2 tw8, float2 tw4, float2 tw2,
        const float2 a[7], float2 out[7]) {
    float2 y[7];
    dft7<false>(a, y);
    #pragma unroll
    for (int k1 = 0; k1 < 7; k1++) {
        float2 twt = sW[t * k1];          // t*k1 <= 186 < 224
        float2 v = cmulf(y[k1], twt);
        bfly(v, t, 16, tw16);
        bfly(v, t,  8, tw8);
        bfly(v, t,  4, tw4);
        bfly(v, t,  2, tw2);
        float2 o;
        o.x = __shfl_xor_sync(0xffffffffu, v.x, 1);
        o.y = __shfl_xor_sync(0xffffffffu, v.y, 1);
        v = (t & 1) ? make_float2(o.x - v.x, o.y - v.y)
                    : make_float2(v.x + o.x, v.y + o.y);
        out[k1] = v;
    }
}

// -------- inverse 224-pt FFT per warp, consuming permuted (DIF) order natively.
__device__ __forceinline__ void fft224_inv(const float2* sW, int t,
        float2 tw16c, float2 tw8c, float2 tw4c, float2 tw2c,
        float2 y[7], float2 xo[7]) {
    #pragma unroll
    for (int k1 = 0; k1 < 7; k1++) {
        float2 v = y[k1];
        float2 o;                                      // stage m=1: plain
        o.x = __shfl_xor_sync(0xffffffffu, v.x, 1);
        o.y = __shfl_xor_sync(0xffffffffu, v.y, 1);
        v = (t & 1) ? csub(o, v) : cadd(v, o);
        ibfly(v, t,  2, tw2c);
        ibfly(v, t,  4, tw4c);
        ibfly(v, t,  8, tw8c);
        ibfly(v, t, 16, tw16c);
        float2 tw = sW[t * k1]; tw.y = -tw.y;          // conj twiddle
        y[k1] = cmulf(v, tw);
    }
    dft7<true>(y, xo);
}

// -------- K0: p = s*(zf + mu*z); r = p; b = 0; partial ||p||^2 --------
__global__ __launch_bounds__(256) void k_init(const float* __restrict__ z,
                                              const float* __restrict__ zf,
                                              const float* __restrict__ miu) {
    float mu = fabsf(miu[0]);
    float rr = 0.f;
    for (int n = blockIdx.x * 256 + threadIdx.x; n < DHW; n += NB_EW * 256) {
        int w = n % Wd;
        int h = (n / Wd) % Hd;
        float s = ((h + w) & 1) ? -1.f : 1.f;
        float pr = s * (zf[n] + mu * z[n]);
        float pi = s * (zf[DHW + n] + mu * z[DHW + n]);
        float2 p = make_float2(pr, pi);
        g_p[n] = p; g_r[n] = p; g_b[n] = make_float2(0.f, 0.f);
        rr = fmaf(pr, pr, fmaf(pi, pi, rr));
    }
    rr = blockReduceF(rr);
    if (threadIdx.x == 0) g_rrp[0][blockIdx.x] = rr;
}

// -------- K1: forward row FFTs with coil expand; direct permuted coalesced store --------
__global__ __launch_bounds__(256) void k_rowfft_fwd(const float* __restrict__ cr,
                                                    const float* __restrict__ ci) {
    __shared__ float2 sW[224];
    int tid = threadIdx.x;
    for (int i = tid; i < 224; i += 256) sW[i] = g_W224[i];
    __syncthreads();
    int warp = tid >> 5, t = tid & 31;
    float2 tw16 = sW[7  * (t & 15)];
    float2 tw8  = sW[14 * (t & 7)];
    float2 tw4  = sW[28 * (t & 3)];
    float2 tw2  = sW[56 * (t & 1)];
    int rid = blockIdx.x * 8 + warp;                 // < 53760
    int c = rid / (Dd * Hd);
    int r2 = rid - c * (Dd * Hd);
    int h = r2 % Hd;
    const float2* prow = g_p + r2 * Wd;
    const float* crr = cr + (c * Hd + h) * Wd;
    const float* cii = ci + (c * Hd + h) * Wd;
    float2 a[7];
    #pragma unroll
    for (int n1 = 0; n1 < 7; n1++) {
        int idx = n1 * 32 + t;
        float2 p = prow[idx];
        float2 co = make_float2(crr[idx], cii[idx]);
        a[n1] = cmulf(p, co);
    }
    float2 out[7];
    fft224_fwd(sW, t, tw16, tw8, tw4, tw2, a, out);
    float2* orow = g_scr + (size_t)rid * Wd;
    #pragma unroll
    for (int k1 = 0; k1 < 7; k1++) orow[k1 * 32 + t] = out[k1];   // permuted, coalesced
}

// -------- forward 448-pt column pass: tile -> registers (k-space, s bit-reversed) --------
__device__ __forceinline__ void colpass_fwd(const float2* tile, const float2* sW,
                                            int g, int s, float2 out[7][4]) {
    float2 z[7][4];
    #pragma unroll
    for (int r = 0; r < 4; r++) {
        int n2 = 16 * r + s;
        float2 xin[7];
        #pragma unroll
        for (int n1 = 0; n1 < 7; n1++) xin[n1] = tile[(n1 * 64 + n2) * TSTR + g];
        float2 y[7];
        dft7<false>(xin, y);
        #pragma unroll
        for (int k1 = 0; k1 < 7; k1++) {
            float2 tw = sW[n2 * k1];                 // <= 378 < 448
            z[k1][r] = cmulf(y[k1], tw);
        }
    }
    // local radix-4 over r (W4 = -i) + twiddle W64^{s*km}
    float2 w1 = sW[7  * s];
    float2 w2 = sW[14 * s];
    float2 w3 = sW[21 * s];
    #pragma unroll
    for (int k1 = 0; k1 < 7; k1++) {
        float2 x0 = z[k1][0], x1 = z[k1][1], x2 = z[k1][2], x3 = z[k1][3];
        float2 t0 = cadd(x0, x2), t2 = csub(x0, x2);
        float2 t1 = cadd(x1, x3), t3 = csub(x1, x3);
        float2 it3 = make_float2(t3.y, -t3.x);        // -i*t3
        z[k1][0] = cadd(t0, t1);
        z[k1][1] = cmulf(cadd(t2, it3), w1);
        z[k1][2] = cmulf(csub(t0, t1), w2);
        z[k1][3] = cmulf(csub(t2, it3), w3);
    }
    // 16-pt DIF over lanes (radix-2 XOR, output bit-reversed in s)
    float2 tw8  = sW[28  * (s & 7)];   // W16^{s&7}
    float2 tw4b = sW[56  * (s & 3)];   // W8^{s&3}
    float2 tw2b = sW[112 * (s & 1)];   // W4^{s&1}
    #pragma unroll
    for (int k1 = 0; k1 < 7; k1++)
        #pragma unroll
        for (int km = 0; km < 4; km++) {
            float2 v = z[k1][km];
            bfly(v, s, 8, tw8);
            bfly(v, s, 4, tw4b);
            bfly(v, s, 2, tw2b);
            float2 o;
            o.x = __shfl_xor_sync(0xffffffffu, v.x, 1);
            o.y = __shfl_xor_sync(0xffffffffu, v.y, 1);
            v = (s & 1) ? make_float2(o.x - v.x, o.y - v.y)
                        : make_float2(v.x + o.x, v.y + o.y);
            out[k1][km] = v;
        }
}

// -------- inverse 448-pt column pass: registers (bitrev s) -> tile (natural h) --------
__device__ __forceinline__ void colpass_inv(float2* tile, const float2* sW,
                                            int g, int s, float2 out[7][4]) {
    // 16-pt DIT over lanes, consuming bit-reversed input
    float2 tw8c  = sW[28  * (s & 7)]; tw8c.y  = -tw8c.y;
    float2 tw4c  = sW[56  * (s & 3)]; tw4c.y  = -tw4c.y;
    float2 tw2c  = sW[112 * (s & 1)]; tw2c.y  = -tw2c.y;
    #pragma unroll
    for (int k1 = 0; k1 < 7; k1++)
        #pragma unroll
        for (int km = 0; km < 4; km++) {
            float2 v = out[k1][km];
            float2 o;                                  // stage m=1: plain
            o.x = __shfl_xor_sync(0xffffffffu, v.x, 1);
            o.y = __shfl_xor_sync(0xffffffffu, v.y, 1);
            v = (s & 1) ? csub(o, v) : cadd(v, o);
            ibfly(v, s, 2, tw2c);
            ibfly(v, s, 4, tw4c);
            ibfly(v, s, 8, tw8c);
            out[k1][km] = v;                           // natural s now
        }
    // conj twiddle W64^{s*km} + inverse radix-4 over km (Wbar4 = +i),
    // then conj twiddle W448^{n2*k1} and inverse dft7 -> natural h into tile
    float2 w1c = sW[7  * s]; w1c.y = -w1c.y;
    float2 w2c = sW[14 * s]; w2c.y = -w2c.y;
    float2 w3c = sW[21 * s]; w3c.y = -w3c.y;
    float2 z[7][4];
    #pragma unroll
    for (int k1 = 0; k1 < 7; k1++) {
        float2 v0 = out[k1][0];
        float2 v1 = cmulf(out[k1][1], w1c);
        float2 v2 = cmulf(out[k1][2], w2c);
        float2 v3 = cmulf(out[k1][3], w3c);
        float2 a = cadd(v0, v2), b = csub(v0, v2);
        float2 cc = cadd(v1, v3), dd = csub(v1, v3);
        float2 idd = make_float2(-dd.y, dd.x);         // +i*dd
        z[k1][0] = cadd(a, cc);
        z[k1][1] = cadd(b, idd);
        z[k1][2] = csub(a, cc);
        z[k1][3] = csub(b, idd);
    }
    #pragma unroll
    for (int r = 0; r < 4; r++) {
        int n2 = 16 * r + s;
        float2 y[7];
        #pragma unroll
        for (int k1 = 0; k1 < 7; k1++) {
            float2 tw = sW[n2 * k1]; tw.y = -tw.y;
            y[k1] = cmulf(z[k1][r], tw);
        }
        float2 xo[7];
        dft7<true>(y, xo);
        #pragma unroll
        for (int n1 = 0; n1 < 7; n1++)
            tile[(n1 * 64 + n2) * TSTR + g] = xo[n1];
    }
}

// -------- K2: column FFT-448 + mask (registers) + column IFFT-448 --------
__global__ __launch_bounds__(256) void k_colfft() {
    extern __shared__ float2 sh[];                   // tile[448*TSTR] ++ W448[448]
    float2* tile = sh;
    float2* sW = sh + 448 * TSTR;
    int tid = threadIdx.x;
    for (int i = tid; i < 448; i += 256) sW[i] = g_W448[i];
    int wt = blockIdx.x % 14;
    int cd = blockIdx.x / 14;                        // c*D + d
    int w0 = wt * 16;
    float2* gbase = g_scr + (size_t)cd * HW;
    int lg = tid & 15, ls = tid >> 4;                // I/O roles (coalesced)
    int s = tid & 15, g = tid >> 4;                  // compute roles (s in half-warp)
    for (int i = 0; i < 28; i++) {
        int h = ls + 16 * i;
        tile[h * TSTR + lg] = gbase[h * Wd + w0 + lg];
    }
    __syncthreads();
    float2 out[7][4];
    colpass_fwd(tile, sW, g, s, out);
    // mask in registers (table permuted to match storage order)
    #pragma unroll
    for (int km = 0; km < 4; km++)
        #pragma unroll
        for (int k1 = 0; k1 < 7; k1++) {
            float mv = g_maskf[(7 * (4 * s + km) + k1) * Wd + w0 + g];
            out[k1][km].x *= mv;
            out[k1][km].y *= mv;
        }
    colpass_inv(tile, sW, g, s, out);                // writes only this thread's slots
    __syncthreads();
    for (int i = 0; i < 28; i++) {
        int h = ls + 16 * i;
        gbase[h * Wd + w0 + lg] = tile[h * TSTR + lg];
    }
}

// -------- K3: DIT inverse row FFTs (permuted input) + conj-coil combine + q; partial q.conj(p)
__global__ __launch_bounds__(256) void k_rowfft_inv(const float* __restrict__ cr,
                                                    const float* __restrict__ ci,
                                                    const float* __restrict__ miu) {
    __shared__ float2 sW[224];
    int tid = threadIdx.x;
    for (int i = tid; i < 224; i += 256) sW[i] = g_W224[i];
    __syncthreads();
    int warp = tid >> 5, t = tid & 31;
    float2 tw16c = sW[7  * (t & 15)]; tw16c.y = -tw16c.y;
    float2 tw8c  = sW[14 * (t & 7)];  tw8c.y  = -tw8c.y;
    float2 tw4c  = sW[28 * (t & 3)];  tw4c.y  = -tw4c.y;
    float2 tw2c  = sW[56 * (t & 1)];  tw2c.y  = -tw2c.y;
    int rid = blockIdx.x * 8 + warp;                 // < 5376 = D*H
    int h = rid % Hd;
    float2 accq[7];
    #pragma unroll
    for (int n1 = 0; n1 < 7; n1++) accq[n1] = make_float2(0.f, 0.f);
    for (int c = 0; c < Cd; c++) {
        const float2* srcrow = g_scr + ((size_t)c * DHW + (size_t)rid * Wd);
        float2 y[7];
        #pragma unroll
        for (int k1 = 0; k1 < 7; k1++) y[k1] = srcrow[k1 * 32 + t];   // coalesced
        float2 xo[7];
        fft224_inv(sW, t, tw16c, tw8c, tw4c, tw2c, y, xo);
        const float* crr = cr + (c * Hd + h) * Wd;
        const float* cii = ci + (c * Hd + h) * Wd;
        #pragma unroll
        for (int n1 = 0; n1 < 7; n1++) {
            int x = n1 * 32 + t;
            float2 co = make_float2(crr[x], -cii[x]);   // conj(coil)
            cmadd(accq[n1], xo[n1], co);
        }
    }
    float mu = fabsf(miu[0]);
    float2 qp = make_float2(0.f, 0.f);
    const float2* prow = g_p + (size_t)rid * Wd;
    float2* qrow = g_q + (size_t)rid * Wd;
    #pragma unroll
    for (int n1 = 0; n1 < 7; n1++) {
        int x = n1 * 32 + t;
        float2 p = prow[x];
        float2 q = make_float2(fmaf(mu, p.x, accq[n1].x), fmaf(mu, p.y, accq[n1].y));
        qrow[x] = q;
        qp.x += q.x * p.x + q.y * p.y;      // q * conj(p)
        qp.y += q.y * p.x - q.x * p.y;
    }
    qp = blockReduceC(qp);
    if (tid == 0) g_qp_part[blockIdx.x] = qp;
}

// -------- fused: alpha = rr/sum(q conj p); b += alpha*p; r -= alpha*q; new ||r||^2 partials
__global__ __launch_bounds__(256) void k_update_br(int it) {
    __shared__ float2 s_al;
    int tid = threadIdx.x;
    float2 qp = make_float2(0.f, 0.f);
    for (int i = tid; i < NB_Q; i += 256) { qp.x += g_qp_part[i].x; qp.y += g_qp_part[i].y; }
    qp = blockReduceC(qp);
    float rrv = 0.f;
    for (int i = tid; i < NB_EW; i += 256) rrv += g_rrp[it & 1][i];
    rrv = blockReduceF(rrv);
    if (tid == 0) {
        float den = qp.x * qp.x + qp.y * qp.y;
        s_al = make_float2(rrv * qp.x / den, -rrv * qp.y / den);
    }
    __syncthreads();
    float2 al = s_al;
    float rr = 0.f;
    for (int n = blockIdx.x * 256 + tid; n < DHW; n += NB_EW * 256) {
        float2 p = g_p[n], q = g_q[n], r = g_r[n], b = g_b[n];
        b.x += al.x * p.x - al.y * p.y;
        b.y += al.x * p.y + al.y * p.x;
        r.x -= al.x * q.x - al.y * q.y;
        r.y -= al.x * q.y + al.y * q.x;
        g_b[n] = b; g_r[n] = r;
        rr = fmaf(r.x, r.x, fmaf(r.y, r.y, rr));
    }
    rr = blockReduceF(rr);
    if (tid == 0) g_rrp[(it + 1) & 1][blockIdx.x] = rr;
}

// -------- fused: beta = rr_new/rr_old; p = r + beta*p --------
__global__ __launch_bounds__(256) void k_update_p(int it) {
    __shared__ float s_be;
    int tid = threadIdx.x;
    float2 v = make_float2(0.f, 0.f);
    for (int i = tid; i < NB_EW; i += 256) {
        v.x += g_rrp[(it + 1) & 1][i];
        v.y += g_rrp[it & 1][i];
    }
    v = blockReduceC(v);
    if (tid == 0) s_be = v.x / v.y;
    __syncthreads();
    float be = s_be;
    for (int n = blockIdx.x * 256 + tid; n < DHW; n += NB_EW * 256) {
        float2 r = g_r[n], p = g_p[n];
        g_p[n] = make_float2(fmaf(be, p.x, r.x), fmaf(be, p.y, r.y));
    }
}

// -------- output: undo sign checkerboard --------
__global__ __launch_bounds__(256) void k_out(float* __restrict__ out) {
    for (int n = blockIdx.x * 256 + threadIdx.x; n < DHW; n += NB_EW * 256) {
        int w = n % Wd;
        int h = (n / Wd) % Hd;
        float s = ((h + w) & 1) ? -1.f : 1.f;
        float2 b = g_b[n];
        out[n] = s * b.x;
        out[DHW + n] = s * b.y;
    }
}

extern "C" void kernel_launch(void* const* d_in, const int* in_sizes, int n_in,
                              void* d_out, int out_size) {
    const float* z    = (const float*)d_in[0];
    const float* zf   = (const float*)d_in[1];
    const float* cr   = (const float*)d_in[2];
    const float* ci   = (const float*)d_in[3];
    const int*   mask = (const int*)d_in[4];
    const float* miu  = (const float*)d_in[5];
    float* out = (float*)d_out;

    const int k2_shmem = 448 * TSTR * (int)sizeof(float2) + 448 * (int)sizeof(float2); // 64512
    cudaFuncSetAttribute(k_colfft, cudaFuncAttributeMaxDynamicSharedMemorySize, k2_shmem);

    k_twiddle<<<1, 448>>>();
    k_maskf<<<(HW + 255) / 256, 256>>>(mask);
    k_init<<<NB_EW, 256>>>(z, zf, miu);
    for (int it = 0; it < 5; ++it) {
        k_rowfft_fwd<<<6720, 256>>>(cr, ci);           // C*D*H/8
        k_colfft<<<1680, 256, k2_shmem>>>();           // C*D*(W/16)
        k_rowfft_inv<<<NB_Q, 256>>>(cr, ci, miu);      // D*H/8
        k_update_br<<<NB_EW, 256>>>(it);
        if (it < 4) k_update_p<<<NB_EW, 256>>>(it);
    }
    k_out<<<NB_EW, 256>>>(out);
}